// round 6
// baseline (speedup 1.0000x reference)
#include <cuda_runtime.h>
#include <math.h>

#define BATCH 2
#define N1 4096
#define N2 4096
#define DD 64
#define KN 16
#define KCC 8
#define CP 80      // padded feature channels (67 / 70 used)
#define CO 128

// ---------------- scratch (static device memory; no runtime alloc) ----------------
__device__ float g_dist[(size_t)BATCH * N1 * N2];        // 134 MB
__device__ float g_F1[BATCH * CP * N1];
__device__ float g_F2[BATCH * CP * N2];
__device__ float g_CB[BATCH * CP * N1];
__device__ float g_nA[BATCH * N1];
__device__ float g_nB[BATCH * N2];
__device__ float g_nC[BATCH * N1];
__device__ int   g_idx1[BATCH * N1 * KN];
__device__ int   g_idx2[BATCH * N1 * KN];
__device__ float g_vw[BATCH * N1 * 3];
__device__ float g_wf[BATCH * N1];
__device__ float g_wr[BATCH * N1];
__device__ float g_p1T[BATCH * N1 * DD];
__device__ float g_p2T[BATCH * N2 * DD];
__device__ float g_x1T[BATCH * N1 * 3];
__device__ float g_x2T[BATCH * N2 * 3];
__device__ float g_p2p[(size_t)BATCH * N1 * CO];

__device__ __forceinline__ float leakyf(float x) { return x >= 0.f ? x : 0.1f * x; }
__device__ __forceinline__ unsigned long long u64min(unsigned long long a, unsigned long long b) {
    return a < b ? a : b;
}

// ---- packed f32x2 helpers (kept for k_mlp) ----
__device__ __forceinline__ unsigned long long bcast2(float x) {
    unsigned long long r;
    asm("mov.b64 %0, {%1,%1};" : "=l"(r) : "f"(x));
    return r;
}
__device__ __forceinline__ unsigned long long fma2(unsigned long long a, unsigned long long b,
                                                   unsigned long long c) {
    unsigned long long d;
    asm("fma.rn.f32x2 %0, %1, %2, %3;" : "=l"(d) : "l"(a), "l"(b), "l"(c));
    return d;
}
__device__ __forceinline__ void unp2(unsigned long long v, float& lo, float& hi) {
    asm("mov.b64 {%0,%1}, %2;" : "=f"(lo), "=f"(hi) : "l"(v));
}

// ---- tf32 helpers ----
__device__ __forceinline__ unsigned int f2tf32(float x) {
    unsigned int r;
    asm("cvt.rna.tf32.f32 %0, %1;" : "=r"(r) : "f"(x));
    return r;
}

#define MMA_TF32(acc, A0, A1, A2, A3, B0, B1)                                   \
    asm volatile("mma.sync.aligned.m16n8k8.row.col.f32.tf32.tf32.f32 "          \
                 "{%0,%1,%2,%3}, {%4,%5,%6,%7}, {%8,%9}, {%0,%1,%2,%3};"        \
                 : "+f"(acc[0]), "+f"(acc[1]), "+f"(acc[2]), "+f"(acc[3])       \
                 : "r"(A0), "r"(A1), "r"(A2), "r"(A3), "r"(B0), "r"(B1))

// ---------------- rigid 3x3 least squares + mask ----------------
__global__ void k_rigid(const float* __restrict__ xyz1, const float* __restrict__ vel1,
                        const float* __restrict__ fcc, const float* __restrict__ fcv,
                        float* __restrict__ out_vw)
{
    int t = blockIdx.x * blockDim.x + threadIdx.x;
    if (t >= BATCH * N1) return;
    int b = t / N1, n = t % N1;
    const float* cc = fcc + (size_t)t * KCC * 3;
    const float* cv = fcv + (size_t)t * KCC;
    double A00 = 1e-6, A01 = 0, A02 = 0, A11 = 1e-6, A12 = 0, A22 = 1e-6;
    double r0 = 0, r1 = 0, r2 = 0;
    for (int k = 0; k < KCC; k++) {
        double x = cc[k * 3 + 0], y = cc[k * 3 + 1], z = cc[k * 3 + 2];
        double inv = 1.0 / sqrt(x * x + y * y + z * z);
        x *= inv; y *= inv; z *= inv;
        A00 += x * x; A01 += x * y; A02 += x * z;
        A11 += y * y; A12 += y * z; A22 += z * z;
        double v = (double)cv[k];
        r0 += x * v; r1 += y * v; r2 += z * v;
    }
    double c00 = A11 * A22 - A12 * A12;
    double c01 = A01 * A22 - A12 * A02;
    double c02 = A01 * A12 - A11 * A02;
    double det = A00 * c00 - A01 * c01 + A02 * c02;
    double id = 1.0 / det;
    double v0 = (r0 * c00 - A01 * (r1 * A22 - A12 * r2) + A02 * (r1 * A12 - A11 * r2)) * id;
    double v1 = (A00 * (r1 * A22 - A12 * r2) - r0 * c01 + A02 * (A01 * r2 - r1 * A02)) * id;
    double v2 = (A00 * (A11 * r2 - r1 * A12) - A01 * (A01 * r2 - r1 * A02) + r0 * c02) * id;

    float fx = xyz1[(b * 3 + 0) * N1 + n];
    float fy = xyz1[(b * 3 + 1) * N1 + n];
    float fz = xyz1[(b * 3 + 2) * N1 + n];
    double inl = 1.0 / sqrt((double)fx * fx + (double)fy * fy + (double)fz * fz);
    double err = fabs((v0 * fx + v1 * fy + v2 * fz) * inl - (double)vel1[t]);
    bool m = (err <= 5.0);
    g_wf[t] = m ? 0.1f : 0.9f;
    g_wr[t] = m ? 0.9f : 0.1f;
    g_vw[t * 3 + 0] = (float)v0;
    g_vw[t * 3 + 1] = (float)v1;
    g_vw[t * 3 + 2] = (float)v2;
    if (out_vw) {
        out_vw[t * 3 + 0] = (float)v0;
        out_vw[t * 3 + 1] = (float)v1;
        out_vw[t * 3 + 2] = (float)v2;
    }
}

// ---------------- fused: weighted feature build + xyz transposes ----------------
__global__ void k_prep(const float* __restrict__ xyz1, const float* __restrict__ xyz2,
                       const float* __restrict__ pts1, const float* __restrict__ pts2,
                       const float* __restrict__ wxyz_p, const float* __restrict__ wpts_p)
{
    float wx = *wxyz_p, wp = *wpts_p;
    const int totalF = BATCH * CP * N1;
    const int tx3 = BATCH * 3 * N1;
    const int total = 2 * totalF + 2 * tx3;
    for (int e = blockIdx.x * blockDim.x + threadIdx.x; e < total;
         e += gridDim.x * blockDim.x) {
        if (e < 2 * totalF) {
            int which = e / totalF;
            int r = e % totalF;
            int b = r / (CP * N1);
            int c = (r / N1) % CP;
            int n = r % N1;
            const float* xyz = which ? xyz2 : xyz1;
            const float* pts = which ? pts2 : pts1;
            float* F = which ? g_F2 : g_F1;
            float v = 0.f;
            if (c < 3) v = wx * xyz[(b * 3 + c) * N1 + n];
            else if (c < 67) v = wp * pts[(b * DD + (c - 3)) * N1 + n];
            F[r] = v;
        } else {
            int r = e - 2 * totalF;
            if (r < tx3) {
                int b = r / (3 * N1), c = (r / N1) % 3, n = r % N1;
                g_x1T[(b * N1 + n) * 3 + c] = xyz1[r];
            } else {
                r -= tx3;
                int b = r / (3 * N1), c = (r / N1) % 3, n = r % N1;
                g_x2T[(b * N2 + n) * 3 + c] = xyz2[r];
            }
        }
    }
}

// ---------------- coalesced tiled transpose: [B][C][N] -> [B][N][C], C=64 ----------------
__global__ void __launch_bounds__(256) k_transp(const float* __restrict__ src1,
                                                const float* __restrict__ src2)
{
    __shared__ float t[32][33];
    int zc = blockIdx.y;
    int ct = zc & 1;
    int b = (zc >> 1) & (BATCH - 1);
    int which = zc >> 2;
    const float* src = which ? src2 : src1;
    float* dst = which ? g_p2T : g_p1T;
    int n0 = blockIdx.x * 32;
    int c0 = ct * 32;
    int lx = threadIdx.x & 31, ly = threadIdx.x >> 5;
    #pragma unroll
    for (int r = 0; r < 4; r++) {
        int c = c0 + ly + r * 8;
        t[ly + r * 8][lx] = src[((size_t)b * DD + c) * N1 + n0 + lx];
    }
    __syncthreads();
    #pragma unroll
    for (int r = 0; r < 4; r++) {
        int n = n0 + ly + r * 8;
        dst[((size_t)b * N1 + n) * DD + c0 + lx] = t[lx][ly + r * 8];
    }
}

// ---------------- all three squared norms in one launch ----------------
__global__ void k_norms()
{
    int t = blockIdx.x * blockDim.x + threadIdx.x;
    if (t >= BATCH * 4096) return;
    int b = t / 4096, n = t % 4096;
    float sA = 0.f, sB = 0.f;
    #pragma unroll 8
    for (int c = 0; c < CP; c++) {
        float a = g_F1[(b * CP + c) * 4096 + n];
        float bb = g_F2[(b * CP + c) * 4096 + n];
        sA += a * a;
        sB += bb * bb;
    }
    g_nA[t] = sA;
    g_nB[t] = sB;
    float wf = g_wf[t], wr = g_wr[t];
    float v0 = g_vw[t * 3 + 0], v1 = g_vw[t * 3 + 1], v2 = g_vw[t * 3 + 2];
    g_nC[t] = wf * wf * sA + wr * wr * (v0 * v0 + v1 * v1 + v2 * v2);
}

// ---------------- comb features for second KNN ----------------
__global__ void k_comb()
{
    const int total = BATCH * CP * N1;
    for (int e = blockIdx.x * blockDim.x + threadIdx.x; e < total;
         e += gridDim.x * blockDim.x) {
        int b = e / (CP * N1);
        int c = (e / N1) % CP;
        int n = e % N1;
        float v = 0.f;
        if (c < 67) v = g_wf[b * N1 + n] * g_F1[e];
        else if (c < 70) v = g_wr[b * N1 + n] * g_vw[(b * N1 + n) * 3 + (c - 67)];
        g_CB[e] = v;
    }
}

// ---------------- distance GEMM on tensor cores (tf32 4-term split) ----------------
// block: 256 threads (8 warps), tile 128x128, K=80 fully staged as tf32 hi/lo.
#define TCS 136   // smem row stride (conflict-free fragment loads)
#define SLAB (CP * TCS)
#define DIST_SMEM ((4 * SLAB + 256) * 4)

__global__ void __launch_bounds__(256) k_dist_tc(int sel)
{
    extern __shared__ float dsm[];
    float* Ah = dsm;
    float* Al = Ah + SLAB;
    float* Bh = Al + SLAB;
    float* Bl = Bh + SLAB;
    float* nAs = Bl + SLAB;   // 128
    float* nBs = nAs + 128;   // 128

    const float* FA = sel ? g_CB : g_F1;
    const float* FB = sel ? g_CB : g_F2;
    const float* nAv = sel ? g_nC : g_nA;
    const float* nBv = sel ? g_nC : g_nB;

    int b = blockIdx.z;
    int i0 = blockIdx.y * 128, j0 = blockIdx.x * 128;
    const float* Ab = FA + (size_t)b * CP * N1 + i0;
    const float* Bb = FB + (size_t)b * CP * N2 + j0;

    int tid = threadIdx.x;
    // stage + split: 80 rows x 32 float4 per matrix
    for (int idx = tid; idx < CP * 32 * 2; idx += 256) {
        int which = idx >= CP * 32;
        int r = which ? idx - CP * 32 : idx;
        int k = r >> 5, c4 = (r & 31) << 2;
        const float* src = which ? Bb : Ab;
        float* Hi = which ? Bh : Ah;
        float* Lo = which ? Bl : Al;
        float4 v = *(const float4*)(src + (size_t)k * 4096 + c4);
        int o = k * TCS + c4;
        unsigned int h;
        h = f2tf32(v.x); Hi[o + 0] = __uint_as_float(h); Lo[o + 0] = __uint_as_float(f2tf32(v.x - __uint_as_float(h)));
        h = f2tf32(v.y); Hi[o + 1] = __uint_as_float(h); Lo[o + 1] = __uint_as_float(f2tf32(v.y - __uint_as_float(h)));
        h = f2tf32(v.z); Hi[o + 2] = __uint_as_float(h); Lo[o + 2] = __uint_as_float(f2tf32(v.z - __uint_as_float(h)));
        h = f2tf32(v.w); Hi[o + 3] = __uint_as_float(h); Lo[o + 3] = __uint_as_float(f2tf32(v.w - __uint_as_float(h)));
    }
    if (tid < 128) {
        nAs[tid] = nAv[b * N1 + i0 + tid];
        nBs[tid] = nBv[b * N2 + j0 + tid];
    }
    __syncthreads();

    int warp = tid >> 5, lane = tid & 31;
    int gid = lane >> 2, tig = lane & 3;
    int m0 = warp * 16;

    float acc[16][4];
    #pragma unroll
    for (int nt = 0; nt < 16; nt++)
        #pragma unroll
        for (int u = 0; u < 4; u++) acc[nt][u] = 0.f;

    int mi = m0 + gid;
    for (int kc = 0; kc < CP; kc += 8) {
        int kr0 = (kc + tig) * TCS;
        int kr1 = (kc + tig + 4) * TCS;
        unsigned int a0h = __float_as_uint(Ah[kr0 + mi]);
        unsigned int a1h = __float_as_uint(Ah[kr0 + mi + 8]);
        unsigned int a2h = __float_as_uint(Ah[kr1 + mi]);
        unsigned int a3h = __float_as_uint(Ah[kr1 + mi + 8]);
        unsigned int a0l = __float_as_uint(Al[kr0 + mi]);
        unsigned int a1l = __float_as_uint(Al[kr0 + mi + 8]);
        unsigned int a2l = __float_as_uint(Al[kr1 + mi]);
        unsigned int a3l = __float_as_uint(Al[kr1 + mi + 8]);
        #pragma unroll
        for (int nt = 0; nt < 16; nt++) {
            int nb = nt * 8 + gid;
            unsigned int b0h = __float_as_uint(Bh[kr0 + nb]);
            unsigned int b1h = __float_as_uint(Bh[kr1 + nb]);
            unsigned int b0l = __float_as_uint(Bl[kr0 + nb]);
            unsigned int b1l = __float_as_uint(Bl[kr1 + nb]);
            MMA_TF32(acc[nt], a0l, a1l, a2l, a3l, b0l, b1l);  // lo*lo (smallest first)
            MMA_TF32(acc[nt], a0l, a1l, a2l, a3l, b0h, b1h);
            MMA_TF32(acc[nt], a0h, a1h, a2h, a3h, b0l, b1l);
            MMA_TF32(acc[nt], a0h, a1h, a2h, a3h, b0h, b1h);
        }
    }

    float* drow = g_dist + (size_t)b * N1 * N2;
    float ni0 = nAs[mi], ni1 = nAs[mi + 8];
    size_t ro0 = (size_t)(i0 + mi) * N2 + j0;
    size_t ro1 = ro0 + (size_t)8 * N2;
    #pragma unroll
    for (int nt = 0; nt < 16; nt++) {
        int jc = nt * 8 + tig * 2;
        float nj0 = nBs[jc], nj1 = nBs[jc + 1];
        float2 o0, o1;
        o0.x = fmaxf(ni0 - 2.f * acc[nt][0] + nj0, 0.f);
        o0.y = fmaxf(ni0 - 2.f * acc[nt][1] + nj1, 0.f);
        o1.x = fmaxf(ni1 - 2.f * acc[nt][2] + nj0, 0.f);
        o1.y = fmaxf(ni1 - 2.f * acc[nt][3] + nj1, 0.f);
        *(float2*)(drow + ro0 + jc) = o0;
        *(float2*)(drow + ro1 + jc) = o1;
    }
}

// ---------------- top-K via incremental segment-min selection ----------------
__global__ void __launch_bounds__(128) k_topk(int sel)
{
    __shared__ unsigned long long keys[N2];
    __shared__ unsigned long long segmin[256];
    __shared__ unsigned long long red[4];
    __shared__ int s_ext;
    int q = blockIdx.x;
    const float* row = g_dist + (size_t)q * N2;
    int* idxo = sel ? g_idx2 : g_idx1;
    int tid = threadIdx.x;

    #pragma unroll
    for (int s2 = 0; s2 < 2; s2++) {
        int seg = tid * 2 + s2;
        int basej = seg * 16;
        unsigned long long mn = ~0ull;
        #pragma unroll
        for (int i = 0; i < 4; i++) {
            float4 f = *(const float4*)(row + basej + i * 4);
            unsigned long long k0 = ((unsigned long long)__float_as_uint(f.x) << 32) | (unsigned)(basej + i * 4 + 0);
            unsigned long long k1 = ((unsigned long long)__float_as_uint(f.y) << 32) | (unsigned)(basej + i * 4 + 1);
            unsigned long long k2 = ((unsigned long long)__float_as_uint(f.z) << 32) | (unsigned)(basej + i * 4 + 2);
            unsigned long long k3 = ((unsigned long long)__float_as_uint(f.w) << 32) | (unsigned)(basej + i * 4 + 3);
            keys[basej + i * 4 + 0] = k0;
            keys[basej + i * 4 + 1] = k1;
            keys[basej + i * 4 + 2] = k2;
            keys[basej + i * 4 + 3] = k3;
            mn = u64min(mn, u64min(u64min(k0, k1), u64min(k2, k3)));
        }
        segmin[seg] = mn;
    }
    __syncthreads();

    for (int k = 0; k < KN; k++) {
        unsigned long long m = u64min(segmin[tid], segmin[tid + 128]);
        #pragma unroll
        for (int o = 16; o; o >>= 1) {
            unsigned long long v = __shfl_xor_sync(0xffffffffu, m, o);
            m = u64min(m, v);
        }
        if ((tid & 31) == 0) red[tid >> 5] = m;
        __syncthreads();
        if (tid == 0) {
            m = u64min(u64min(red[0], red[1]), u64min(red[2], red[3]));
            int j = (int)(unsigned)(m & 0xffffffffULL);
            idxo[q * KN + k] = j;
            keys[j] = ~0ull;
            s_ext = j;
        }
        __syncthreads();
        if (k < KN - 1) {
            int seg = s_ext >> 4;
            if (tid < 16) {
                unsigned long long v = keys[seg * 16 + tid];
                #pragma unroll
                for (int o = 8; o; o >>= 1) {
                    unsigned long long w = __shfl_xor_sync(0xffffu, v, o);
                    v = u64min(v, w);
                }
                if (tid == 0) segmin[seg] = v;
            }
            __syncthreads();
        }
    }
}

// ---------------- fused MLP: 8x8 register-tiled block GEMM (FFMA2 packed) ----------------
#define TNP 8
#define AW 132
#define OFF_W    0
#define OFF_A    (131 * AW)
#define OFF_B    (OFF_A + 131 * AW)
#define OFF_H2   (OFF_B + 128 * AW)
#define OFF_SW2  (OFF_H2 + 128 * 8)
#define OFF_SB2  (OFF_SW2 + 128 * 8)
#define OFF_PS   (OFF_SB2 + 128)
#define OFF_IDX  (OFF_PS + 16 * 128)
#define MLP_SMEM ((OFF_IDX + 128) * 4)

template<int KIN>
__device__ __forceinline__ void mm8x8p(const float* __restrict__ A, const float* __restrict__ W,
                                       int tx, int ty, unsigned long long (&acc)[8][4])
{
    #pragma unroll 4
    for (int kk = 0; kk < KIN; kk++) {
        ulonglong2 a01 = *(const ulonglong2*)(A + kk * AW + tx * 8);
        ulonglong2 a23 = *(const ulonglong2*)(A + kk * AW + tx * 8 + 4);
        float4 w0 = *(const float4*)(W + kk * AW + ty * 8);
        float4 w1 = *(const float4*)(W + kk * AW + ty * 8 + 4);
        unsigned long long av[4] = {a01.x, a01.y, a23.x, a23.y};
        unsigned long long wb[8];
        wb[0] = bcast2(w0.x); wb[1] = bcast2(w0.y); wb[2] = bcast2(w0.z); wb[3] = bcast2(w0.w);
        wb[4] = bcast2(w1.x); wb[5] = bcast2(w1.y); wb[6] = bcast2(w1.z); wb[7] = bcast2(w1.w);
        #pragma unroll
        for (int u = 0; u < 8; u++)
            #pragma unroll
            for (int vp = 0; vp < 4; vp++)
                acc[u][vp] = fma2(wb[u], av[vp], acc[u][vp]);
    }
}

__device__ __forceinline__ void store_leaky8(float* dst, const unsigned long long (&acc)[8][4],
                                             int u)
{
    float x[8];
    unp2(acc[u][0], x[0], x[1]);
    unp2(acc[u][1], x[2], x[3]);
    unp2(acc[u][2], x[4], x[5]);
    unp2(acc[u][3], x[6], x[7]);
    float4 o0, o1;
    o0.x = leakyf(x[0]); o0.y = leakyf(x[1]); o0.z = leakyf(x[2]); o0.w = leakyf(x[3]);
    o1.x = leakyf(x[4]); o1.y = leakyf(x[5]); o1.z = leakyf(x[6]); o1.w = leakyf(x[7]);
    *(float4*)dst = o0;
    *(float4*)(dst + 4) = o1;
}

__global__ void __launch_bounds__(256) k_mlp(
    const float* __restrict__ w0g, const float* __restrict__ b0g,
    const float* __restrict__ w1g, const float* __restrict__ b1g,
    const float* __restrict__ w2g, const float* __restrict__ b2g,
    const float* __restrict__ n1w0, const float* __restrict__ n1b0,
    const float* __restrict__ n1w1, const float* __restrict__ n1b1,
    const float* __restrict__ n1w2, const float* __restrict__ n1b2)
{
    extern __shared__ float sm[];
    float* Wsm = sm + OFF_W;
    float* Abuf = sm + OFF_A;
    float* Bbuf = sm + OFF_B;
    float* h2s = sm + OFF_H2;
    float* sw2 = sm + OFF_SW2;
    float* sb2 = sm + OFF_SB2;
    float* ps  = sm + OFF_PS;
    int* idxs = (int*)(sm + OFF_IDX);

    int tid = threadIdx.x;
    int tx = tid & 15, ty = tid >> 4;
    int base = blockIdx.x * TNP;

    if (tid < 128) {
        idxs[tid] = g_idx1[base * KN + tid];
        #pragma unroll
        for (int r = 0; r < 8; r++) sw2[tid + 128 * r] = n1w2[tid + 128 * r];
        sb2[tid] = n1b2[tid];
    }
    __syncthreads();

    // stage A [131][128]
    for (int e = tid; e < 131 * 128; e += 256) {
        int i = e >> 7, col = e & 127;
        int tn = col >> 4;
        int pt = base + tn;
        int b = pt >> 12;
        int j = idxs[col];
        float v;
        if (i < 64) v = g_p1T[(size_t)pt * DD + i];
        else if (i < 128) v = g_p2T[((size_t)b * N2 + j) * DD + (i - 64)];
        else v = g_x2T[(b * N2 + j) * 3 + (i - 128)] - g_x1T[pt * 3 + (i - 128)];
        Abuf[i * AW + col] = v;
    }
    // stage W0 transposed [in 131][out 128]
    for (int e = tid; e < 128 * 131; e += 256) {
        int i = e % 131, c = e / 131;
        Wsm[i * AW + c] = w0g[e];
    }
    __syncthreads();

    // weight-net 1 (3->8->8) per column -> h2s[col][8]
    if (tid < 128) {
        int col = tid;
        float dx0 = Abuf[128 * AW + col];
        float dx1 = Abuf[129 * AW + col];
        float dx2 = Abuf[130 * AW + col];
        float h[8];
        #pragma unroll
        for (int j = 0; j < 8; j++) {
            float s = n1w0[j * 3 + 0] * dx0 + n1w0[j * 3 + 1] * dx1 + n1w0[j * 3 + 2] * dx2 + n1b0[j];
            h[j] = fmaxf(s, 0.f);
        }
        #pragma unroll
        for (int j = 0; j < 8; j++) {
            float s = n1b1[j];
            #pragma unroll
            for (int m = 0; m < 8; m++) s += n1w1[j * 8 + m] * h[m];
            h2s[col * 8 + j] = fmaxf(s, 0.f);
        }
    }
    __syncthreads();

    unsigned long long bias0[8], bias1[8], bias2[8];
    #pragma unroll
    for (int u = 0; u < 8; u++) {
        bias0[u] = bcast2(b0g[ty * 8 + u]);
        bias1[u] = bcast2(b1g[ty * 8 + u]);
        bias2[u] = bcast2(b2g[ty * 8 + u]);
    }

    unsigned long long acc[8][4];

    // ---- layer 1: 131 -> 128, leaky ----
    #pragma unroll
    for (int u = 0; u < 8; u++)
        #pragma unroll
        for (int vp = 0; vp < 4; vp++) acc[u][vp] = bias0[u];
    mm8x8p<131>(Abuf, Wsm, tx, ty, acc);
    #pragma unroll
    for (int u = 0; u < 8; u++)
        store_leaky8(Bbuf + (ty * 8 + u) * AW + tx * 8, acc, u);
    __syncthreads();

    // stage W1
    for (int e = tid; e < 128 * 128; e += 256) {
        int i = e & 127, c = e >> 7;
        Wsm[i * AW + c] = w1g[e];
    }
    __syncthreads();

    // ---- layer 2: 128 -> 128, leaky ----
    #pragma unroll
    for (int u = 0; u < 8; u++)
        #pragma unroll
        for (int vp = 0; vp < 4; vp++) acc[u][vp] = bias1[u];
    mm8x8p<128>(Bbuf, Wsm, tx, ty, acc);
    #pragma unroll
    for (int u = 0; u < 8; u++)
        store_leaky8(Abuf + (ty * 8 + u) * AW + tx * 8, acc, u);
    __syncthreads();

    // stage W2
    for (int e = tid; e < 128 * 128; e += 256) {
        int i = e & 127, c = e >> 7;
        Wsm[i * AW + c] = w2g[e];
    }
    __syncthreads();

    // ---- S matrix -> Bbuf ----
    {
        int col = tid >> 1, chalf = tid & 1;
        float hj[8];
        #pragma unroll
        for (int j = 0; j < 8; j++) hj[j] = h2s[col * 8 + j];
        #pragma unroll 4
        for (int cc = 0; cc < 64; cc++) {
            int c = chalf * 64 + cc;
            float s = sb2[c];
            #pragma unroll
            for (int j = 0; j < 8; j++) s += sw2[c * 8 + j] * hj[j];
            Bbuf[col * AW + c] = fmaxf(s, 0.f);
        }
    }

    // ---- layer 3: 128 -> 128 ----
    #pragma unroll
    for (int u = 0; u < 8; u++)
        #pragma unroll
        for (int vp = 0; vp < 4; vp++) acc[u][vp] = bias2[u];
    mm8x8p<128>(Abuf, Wsm, tx, ty, acc);
    __syncthreads();   // S writes visible

    // ---- epilogue ----
    {
        float partial[8];
        #pragma unroll
        for (int u = 0; u < 8; u++) partial[u] = 0.f;
        #pragma unroll
        for (int vp = 0; vp < 4; vp++) {
            float e0[8], e1[8];
            #pragma unroll
            for (int u = 0; u < 8; u++) unp2(acc[u][vp], e0[u], e1[u]);
            {
                int col = tx * 8 + 2 * vp;
                float4 s0 = *(const float4*)(Bbuf + col * AW + ty * 8);
                float4 s1 = *(const float4*)(Bbuf + col * AW + ty * 8 + 4);
                float s[8] = {s0.x, s0.y, s0.z, s0.w, s1.x, s1.y, s1.z, s1.w};
                #pragma unroll
                for (int u = 0; u < 8; u++) partial[u] += s[u] * leakyf(e0[u]);
            }
            {
                int col = tx * 8 + 2 * vp + 1;
                float4 s0 = *(const float4*)(Bbuf + col * AW + ty * 8);
                float4 s1 = *(const float4*)(Bbuf + col * AW + ty * 8 + 4);
                float s[8] = {s0.x, s0.y, s0.z, s0.w, s1.x, s1.y, s1.z, s1.w};
                #pragma unroll
                for (int u = 0; u < 8; u++) partial[u] += s[u] * leakyf(e1[u]);
            }
        }
        #pragma unroll
        for (int u = 0; u < 8; u++) ps[tx * 128 + ty * 8 + u] = partial[u];
    }
    __syncthreads();
    for (int e = tid; e < 1024; e += 256) {
        int tn = e >> 7, c = e & 127;
        g_p2p[(size_t)(base + tn) * CO + c] = ps[(2 * tn) * 128 + c] + ps[(2 * tn + 1) * 128 + c];
    }
}

// ---------------- patch aggregation ----------------
__global__ void __launch_bounds__(128) k_patch(
    const float* __restrict__ n2w0, const float* __restrict__ n2b0,
    const float* __restrict__ n2w1, const float* __restrict__ n2b1,
    const float* __restrict__ n2w2, const float* __restrict__ n2b2,
    float* __restrict__ out)
{
    __shared__ float h2s[16][8];
    __shared__ int js[16];
    int q = blockIdx.x;
    int b = q / N1, n = q % N1;
    int tid = threadIdx.x;
    if (tid < 16) {
        int j = g_idx2[q * KN + tid];
        js[tid] = j;
        float dx0 = g_x1T[(b * N1 + j) * 3 + 0] - g_x1T[q * 3 + 0];
        float dx1 = g_x1T[(b * N1 + j) * 3 + 1] - g_x1T[q * 3 + 1];
        float dx2 = g_x1T[(b * N1 + j) * 3 + 2] - g_x1T[q * 3 + 2];
        float h[8];
        #pragma unroll
        for (int jj = 0; jj < 8; jj++) {
            float s = n2w0[jj * 3 + 0] * dx0 + n2w0[jj * 3 + 1] * dx1 + n2w0[jj * 3 + 2] * dx2 + n2b0[jj];
            h[jj] = fmaxf(s, 0.f);
        }
        #pragma unroll
        for (int jj = 0; jj < 8; jj++) {
            float s = n2b1[jj];
            #pragma unroll
            for (int m = 0; m < 8; m++) s += n2w1[jj * 8 + m] * h[m];
            h2s[tid][jj] = fmaxf(s, 0.f);
        }
    }
    __syncthreads();
    int c = tid;
    float w2r[8];
    #pragma unroll
    for (int j = 0; j < 8; j++) w2r[j] = n2w2[c * 8 + j];
    float bc = n2b2[c];
    float acc = 0.f;
    #pragma unroll
    for (int k = 0; k < KN; k++) {
        float s = bc;
        #pragma unroll
        for (int j = 0; j < 8; j++) s += w2r[j] * h2s[k][j];
        s = fmaxf(s, 0.f);
        acc += s * g_p2p[((size_t)b * N1 + js[k]) * CO + c];
    }
    out[(size_t)b * CO * N1 + (size_t)c * N1 + n] = acc;
}

// ---------------- launch ----------------
extern "C" void kernel_launch(void* const* d_in, const int* in_sizes, int n_in,
                              void* d_out, int out_size)
{
    int s = (n_in >= 31) ? 0 : -2;
    const float* xyz1 = (const float*)d_in[0];
    const float* xyz2 = (const float*)d_in[1];
    const float* pts1 = (const float*)d_in[2];
    const float* pts2 = (const float*)d_in[3];
    const float* vel1 = (const float*)d_in[4];
    const float* fcc  = (const float*)d_in[8 + s];
    const float* fcv  = (const float*)d_in[9 + s];
    const float* wxyz = (const float*)d_in[10 + s];
    const float* wpts = (const float*)d_in[12 + s];
    const float* mw0 = (const float*)d_in[13 + s];
    const float* mb0 = (const float*)d_in[14 + s];
    const float* mw1 = (const float*)d_in[15 + s];
    const float* mb1 = (const float*)d_in[16 + s];
    const float* mw2 = (const float*)d_in[17 + s];
    const float* mb2 = (const float*)d_in[18 + s];
    const float* n1w0 = (const float*)d_in[19 + s];
    const float* n1b0 = (const float*)d_in[20 + s];
    const float* n2w0 = (const float*)d_in[21 + s];
    const float* n2b0 = (const float*)d_in[22 + s];
    const float* n1w1 = (const float*)d_in[23 + s];
    const float* n1b1 = (const float*)d_in[24 + s];
    const float* n2w1 = (const float*)d_in[25 + s];
    const float* n2b1 = (const float*)d_in[26 + s];
    const float* n1w2 = (const float*)d_in[27 + s];
    const float* n1b2 = (const float*)d_in[28 + s];
    const float* n2w2 = (const float*)d_in[29 + s];
    const float* n2b2 = (const float*)d_in[30 + s];

    float* out = (float*)d_out;
    const int patch_elems = BATCH * CO * N1;
    const int vw_elems = BATCH * N1 * 3;
    float* out_vw = (out_size >= patch_elems + vw_elems) ? (out + patch_elems) : nullptr;

    cudaFuncSetAttribute(k_mlp, cudaFuncAttributeMaxDynamicSharedMemorySize, (int)MLP_SMEM);
    cudaFuncSetAttribute(k_dist_tc, cudaFuncAttributeMaxDynamicSharedMemorySize, (int)DIST_SMEM);

    const int prep_total = 2 * BATCH * CP * N1 + 2 * BATCH * 3 * N1;
    dim3 gg(N2 / 128, N1 / 128, BATCH);
    dim3 gt(N1 / 32, 2 * BATCH * 2);

    // dist_tc is the 4th launch -> ncu capture lands on it
    k_rigid<<<(BATCH * N1 + 127) / 128, 128>>>(xyz1, vel1, fcc, fcv, out_vw);
    k_prep<<<(prep_total + 255) / 256, 256>>>(xyz1, xyz2, pts1, pts2, wxyz, wpts);
    k_norms<<<(BATCH * 4096 + 127) / 128, 128>>>();
    k_dist_tc<<<gg, 256, DIST_SMEM>>>(0);
    k_topk<<<BATCH * N1, 128>>>(0);
    k_transp<<<gt, 256>>>(pts1, pts2);
    k_mlp<<<(BATCH * N1) / TNP, 256, MLP_SMEM>>>(mw0, mb0, mw1, mb1, mw2, mb2,
                                                 n1w0, n1b0, n1w1, n1b1, n1w2, n1b2);
    k_comb<<<(BATCH * CP * N1 + 255) / 256, 256>>>();
    k_dist_tc<<<gg, 256, DIST_SMEM>>>(1);
    k_topk<<<BATCH * N1, 128>>>(1);
    k_patch<<<BATCH * N1, 128>>>(n2w0, n2b0, n2w1, n2b1, n2w2, n2b2, out);
}

// round 7
// speedup vs baseline: 1.1193x; 1.1193x over previous
#include <cuda_runtime.h>
#include <math.h>

#define BATCH 2
#define N1 4096
#define N2 4096
#define DD 64
#define KN 16
#define KCC 8
#define CP 80      // padded feature channels (67 / 70 used)
#define CO 128

// ---------------- scratch (static device memory; no runtime alloc) ----------------
__device__ float g_dist[(size_t)BATCH * N1 * N2];        // 134 MB
__device__ float g_F1[BATCH * CP * N1];
__device__ float g_F2[BATCH * CP * N2];
__device__ float g_CB[BATCH * CP * N1];
__device__ float g_nA[BATCH * N1];
__device__ float g_nB[BATCH * N2];
__device__ float g_nC[BATCH * N1];
__device__ int   g_idx1[BATCH * N1 * KN];
__device__ int   g_idx2[BATCH * N1 * KN];
__device__ float g_vw[BATCH * N1 * 3];
__device__ float g_wf[BATCH * N1];
__device__ float g_wr[BATCH * N1];
__device__ float g_p1T[BATCH * N1 * DD];
__device__ float g_p2T[BATCH * N2 * DD];
__device__ float g_x1T[BATCH * N1 * 3];
__device__ float g_x2T[BATCH * N2 * 3];
__device__ float g_p2p[(size_t)BATCH * N1 * CO];

__device__ __forceinline__ float leakyf(float x) { return x >= 0.f ? x : 0.1f * x; }
__device__ __forceinline__ unsigned long long u64min(unsigned long long a, unsigned long long b) {
    return a < b ? a : b;
}

// ---- packed f32x2 helpers (kept for k_mlp) ----
__device__ __forceinline__ unsigned long long bcast2(float x) {
    unsigned long long r;
    asm("mov.b64 %0, {%1,%1};" : "=l"(r) : "f"(x));
    return r;
}
__device__ __forceinline__ unsigned long long fma2(unsigned long long a, unsigned long long b,
                                                   unsigned long long c) {
    unsigned long long d;
    asm("fma.rn.f32x2 %0, %1, %2, %3;" : "=l"(d) : "l"(a), "l"(b), "l"(c));
    return d;
}
__device__ __forceinline__ void unp2(unsigned long long v, float& lo, float& hi) {
    asm("mov.b64 {%0,%1}, %2;" : "=f"(lo), "=f"(hi) : "l"(v));
}

// ---- tf32 helpers ----
__device__ __forceinline__ float f2tf32f(float x) {
    unsigned int r;
    asm("cvt.rna.tf32.f32 %0, %1;" : "=r"(r) : "f"(x));
    return __uint_as_float(r);
}

#define MMA_TF32(acc, A0, A1, A2, A3, B0, B1)                                   \
    asm volatile("mma.sync.aligned.m16n8k8.row.col.f32.tf32.tf32.f32 "          \
                 "{%0,%1,%2,%3}, {%4,%5,%6,%7}, {%8,%9}, {%0,%1,%2,%3};"        \
                 : "+f"(acc[0]), "+f"(acc[1]), "+f"(acc[2]), "+f"(acc[3])       \
                 : "r"(__float_as_uint(A0)), "r"(__float_as_uint(A1)),          \
                   "r"(__float_as_uint(A2)), "r"(__float_as_uint(A3)),          \
                   "r"(__float_as_uint(B0)), "r"(__float_as_uint(B1)))

// ---------------- rigid 3x3 least squares + mask ----------------
__global__ void k_rigid(const float* __restrict__ xyz1, const float* __restrict__ vel1,
                        const float* __restrict__ fcc, const float* __restrict__ fcv,
                        float* __restrict__ out_vw)
{
    int t = blockIdx.x * blockDim.x + threadIdx.x;
    if (t >= BATCH * N1) return;
    int b = t / N1, n = t % N1;
    const float* cc = fcc + (size_t)t * KCC * 3;
    const float* cv = fcv + (size_t)t * KCC;
    double A00 = 1e-6, A01 = 0, A02 = 0, A11 = 1e-6, A12 = 0, A22 = 1e-6;
    double r0 = 0, r1 = 0, r2 = 0;
    for (int k = 0; k < KCC; k++) {
        double x = cc[k * 3 + 0], y = cc[k * 3 + 1], z = cc[k * 3 + 2];
        double inv = 1.0 / sqrt(x * x + y * y + z * z);
        x *= inv; y *= inv; z *= inv;
        A00 += x * x; A01 += x * y; A02 += x * z;
        A11 += y * y; A12 += y * z; A22 += z * z;
        double v = (double)cv[k];
        r0 += x * v; r1 += y * v; r2 += z * v;
    }
    double c00 = A11 * A22 - A12 * A12;
    double c01 = A01 * A22 - A12 * A02;
    double c02 = A01 * A12 - A11 * A02;
    double det = A00 * c00 - A01 * c01 + A02 * c02;
    double id = 1.0 / det;
    double v0 = (r0 * c00 - A01 * (r1 * A22 - A12 * r2) + A02 * (r1 * A12 - A11 * r2)) * id;
    double v1 = (A00 * (r1 * A22 - A12 * r2) - r0 * c01 + A02 * (A01 * r2 - r1 * A02)) * id;
    double v2 = (A00 * (A11 * r2 - r1 * A12) - A01 * (A01 * r2 - r1 * A02) + r0 * c02) * id;

    float fx = xyz1[(b * 3 + 0) * N1 + n];
    float fy = xyz1[(b * 3 + 1) * N1 + n];
    float fz = xyz1[(b * 3 + 2) * N1 + n];
    double inl = 1.0 / sqrt((double)fx * fx + (double)fy * fy + (double)fz * fz);
    double err = fabs((v0 * fx + v1 * fy + v2 * fz) * inl - (double)vel1[t]);
    bool m = (err <= 5.0);
    g_wf[t] = m ? 0.1f : 0.9f;
    g_wr[t] = m ? 0.9f : 0.1f;
    g_vw[t * 3 + 0] = (float)v0;
    g_vw[t * 3 + 1] = (float)v1;
    g_vw[t * 3 + 2] = (float)v2;
    if (out_vw) {
        out_vw[t * 3 + 0] = (float)v0;
        out_vw[t * 3 + 1] = (float)v1;
        out_vw[t * 3 + 2] = (float)v2;
    }
}

// ---------------- fused: weighted feature build + xyz transposes ----------------
__global__ void k_prep(const float* __restrict__ xyz1, const float* __restrict__ xyz2,
                       const float* __restrict__ pts1, const float* __restrict__ pts2,
                       const float* __restrict__ wxyz_p, const float* __restrict__ wpts_p)
{
    float wx = *wxyz_p, wp = *wpts_p;
    const int totalF = BATCH * CP * N1;
    const int tx3 = BATCH * 3 * N1;
    const int total = 2 * totalF + 2 * tx3;
    for (int e = blockIdx.x * blockDim.x + threadIdx.x; e < total;
         e += gridDim.x * blockDim.x) {
        if (e < 2 * totalF) {
            int which = e / totalF;
            int r = e % totalF;
            int b = r / (CP * N1);
            int c = (r / N1) % CP;
            int n = r % N1;
            const float* xyz = which ? xyz2 : xyz1;
            const float* pts = which ? pts2 : pts1;
            float* F = which ? g_F2 : g_F1;
            float v = 0.f;
            if (c < 3) v = wx * xyz[(b * 3 + c) * N1 + n];
            else if (c < 67) v = wp * pts[(b * DD + (c - 3)) * N1 + n];
            F[r] = v;
        } else {
            int r = e - 2 * totalF;
            if (r < tx3) {
                int b = r / (3 * N1), c = (r / N1) % 3, n = r % N1;
                g_x1T[(b * N1 + n) * 3 + c] = xyz1[r];
            } else {
                r -= tx3;
                int b = r / (3 * N1), c = (r / N1) % 3, n = r % N1;
                g_x2T[(b * N2 + n) * 3 + c] = xyz2[r];
            }
        }
    }
}

// ---------------- coalesced tiled transpose: [B][C][N] -> [B][N][C], C=64 ----------------
__global__ void __launch_bounds__(256) k_transp(const float* __restrict__ src1,
                                                const float* __restrict__ src2)
{
    __shared__ float t[32][33];
    int zc = blockIdx.y;
    int ct = zc & 1;
    int b = (zc >> 1) & (BATCH - 1);
    int which = zc >> 2;
    const float* src = which ? src2 : src1;
    float* dst = which ? g_p2T : g_p1T;
    int n0 = blockIdx.x * 32;
    int c0 = ct * 32;
    int lx = threadIdx.x & 31, ly = threadIdx.x >> 5;
    #pragma unroll
    for (int r = 0; r < 4; r++) {
        int c = c0 + ly + r * 8;
        t[ly + r * 8][lx] = src[((size_t)b * DD + c) * N1 + n0 + lx];
    }
    __syncthreads();
    #pragma unroll
    for (int r = 0; r < 4; r++) {
        int n = n0 + ly + r * 8;
        dst[((size_t)b * N1 + n) * DD + c0 + lx] = t[lx][ly + r * 8];
    }
}

// ---------------- all three squared norms in one launch ----------------
__global__ void k_norms()
{
    int t = blockIdx.x * blockDim.x + threadIdx.x;
    if (t >= BATCH * 4096) return;
    int b = t / 4096, n = t % 4096;
    float sA = 0.f, sB = 0.f;
    #pragma unroll 8
    for (int c = 0; c < CP; c++) {
        float a = g_F1[(b * CP + c) * 4096 + n];
        float bb = g_F2[(b * CP + c) * 4096 + n];
        sA += a * a;
        sB += bb * bb;
    }
    g_nA[t] = sA;
    g_nB[t] = sB;
    float wf = g_wf[t], wr = g_wr[t];
    float v0 = g_vw[t * 3 + 0], v1 = g_vw[t * 3 + 1], v2 = g_vw[t * 3 + 2];
    g_nC[t] = wf * wf * sA + wr * wr * (v0 * v0 + v1 * v1 + v2 * v2);
}

// ---------------- comb features for second KNN ----------------
__global__ void k_comb()
{
    const int total = BATCH * CP * N1;
    for (int e = blockIdx.x * blockDim.x + threadIdx.x; e < total;
         e += gridDim.x * blockDim.x) {
        int b = e / (CP * N1);
        int c = (e / N1) % CP;
        int n = e % N1;
        float v = 0.f;
        if (c < 67) v = g_wf[b * N1 + n] * g_F1[e];
        else if (c < 70) v = g_wr[b * N1 + n] * g_vw[(b * N1 + n) * 3 + (c - 67)];
        g_CB[e] = v;
    }
}

// ---------------- distance GEMM on tensor cores (3xTF32, hi/lo interleaved) ----------------
// 256 threads (8 warps), tile 128x128, K staged in 2 chunks of 40 rows.
// smem row stride 132 float2 (264 floats; 264 mod 32 == 8 -> conflict-free fragments).
#define CPK 40
#define S2 132
#define SLAB2 (CPK * S2)
#define DIST_SMEM ((2 * SLAB2 * 2 + 256) * 4)

__global__ void __launch_bounds__(256) k_dist_tc(int sel)
{
    extern __shared__ float2 dsm2[];
    float2* As2 = dsm2;                 // [CPK][S2] (hi,lo)
    float2* Bs2 = As2 + SLAB2;
    float* nAs = (float*)(Bs2 + SLAB2); // 128
    float* nBs = nAs + 128;             // 128

    const float* FA = sel ? g_CB : g_F1;
    const float* FB = sel ? g_CB : g_F2;
    const float* nAv = sel ? g_nC : g_nA;
    const float* nBv = sel ? g_nC : g_nB;

    int b = blockIdx.z;
    int i0 = blockIdx.y * 128, j0 = blockIdx.x * 128;
    const float* Asrc = FA + (size_t)b * CP * N1 + i0;
    const float* Bsrc = FB + (size_t)b * CP * N2 + j0;

    int tid = threadIdx.x;
    if (tid < 128) {
        nAs[tid] = nAv[b * N1 + i0 + tid];
        nBs[tid] = nBv[b * N2 + j0 + tid];
    }

    int warp = tid >> 5, lane = tid & 31;
    int gid = lane >> 2, tig = lane & 3;
    int mi = warp * 16 + gid;

    float acc[16][4];
    #pragma unroll
    for (int nt = 0; nt < 16; nt++)
        #pragma unroll
        for (int u = 0; u < 4; u++) acc[nt][u] = 0.f;

    for (int kb = 0; kb < CP; kb += CPK) {
        // stage chunk: CPK rows x 32 float4 x 2 matrices
        for (int idx = tid; idx < CPK * 32 * 2; idx += 256) {
            int which = idx >= CPK * 32;
            int r = which ? idx - CPK * 32 : idx;
            int k = r >> 5, c4 = (r & 31) << 2;
            const float* src = which ? Bsrc : Asrc;
            float2* dst = (which ? Bs2 : As2) + k * S2 + c4;
            float4 v = *(const float4*)(src + (size_t)(kb + k) * 4096 + c4);
            float h;
            h = f2tf32f(v.x); dst[0] = make_float2(h, f2tf32f(v.x - h));
            h = f2tf32f(v.y); dst[1] = make_float2(h, f2tf32f(v.y - h));
            h = f2tf32f(v.z); dst[2] = make_float2(h, f2tf32f(v.z - h));
            h = f2tf32f(v.w); dst[3] = make_float2(h, f2tf32f(v.w - h));
        }
        __syncthreads();

        #pragma unroll
        for (int kk = 0; kk < CPK; kk += 8) {
            const float2* r0 = As2 + (kk + tig) * S2;
            const float2* r1 = As2 + (kk + tig + 4) * S2;
            float2 a0 = r0[mi], a1 = r0[mi + 8];
            float2 a2 = r1[mi], a3 = r1[mi + 8];
            const float2* q0 = Bs2 + (kk + tig) * S2;
            const float2* q1 = Bs2 + (kk + tig + 4) * S2;
            #pragma unroll
            for (int nt = 0; nt < 16; nt++) {
                int nb = nt * 8 + gid;
                float2 b0 = q0[nb], b1 = q1[nb];
                MMA_TF32(acc[nt], a0.y, a1.y, a2.y, a3.y, b0.x, b1.x);  // lo*hi
                MMA_TF32(acc[nt], a0.x, a1.x, a2.x, a3.x, b0.y, b1.y);  // hi*lo
                MMA_TF32(acc[nt], a0.x, a1.x, a2.x, a3.x, b0.x, b1.x);  // hi*hi
            }
        }
        __syncthreads();
    }

    float* drow = g_dist + (size_t)b * N1 * N2;
    float ni0 = nAs[mi], ni1 = nAs[mi + 8];
    size_t ro0 = (size_t)(i0 + mi) * N2 + j0;
    size_t ro1 = ro0 + (size_t)8 * N2;
    #pragma unroll
    for (int nt = 0; nt < 16; nt++) {
        int jc = nt * 8 + tig * 2;
        float nj0 = nBs[jc], nj1 = nBs[jc + 1];
        float2 o0, o1;
        o0.x = fmaxf(ni0 - 2.f * acc[nt][0] + nj0, 0.f);
        o0.y = fmaxf(ni0 - 2.f * acc[nt][1] + nj1, 0.f);
        o1.x = fmaxf(ni1 - 2.f * acc[nt][2] + nj0, 0.f);
        o1.y = fmaxf(ni1 - 2.f * acc[nt][3] + nj1, 0.f);
        *(float2*)(drow + ro0 + jc) = o0;
        *(float2*)(drow + ro1 + jc) = o1;
    }
}

// ---------------- top-K via incremental segment-min selection ----------------
__global__ void __launch_bounds__(128) k_topk(int sel)
{
    __shared__ unsigned long long keys[N2];
    __shared__ unsigned long long segmin[256];
    __shared__ unsigned long long red[4];
    __shared__ int s_ext;
    int q = blockIdx.x;
    const float* row = g_dist + (size_t)q * N2;
    int* idxo = sel ? g_idx2 : g_idx1;
    int tid = threadIdx.x;

    #pragma unroll
    for (int s2 = 0; s2 < 2; s2++) {
        int seg = tid * 2 + s2;
        int basej = seg * 16;
        unsigned long long mn = ~0ull;
        #pragma unroll
        for (int i = 0; i < 4; i++) {
            float4 f = *(const float4*)(row + basej + i * 4);
            unsigned long long k0 = ((unsigned long long)__float_as_uint(f.x) << 32) | (unsigned)(basej + i * 4 + 0);
            unsigned long long k1 = ((unsigned long long)__float_as_uint(f.y) << 32) | (unsigned)(basej + i * 4 + 1);
            unsigned long long k2 = ((unsigned long long)__float_as_uint(f.z) << 32) | (unsigned)(basej + i * 4 + 2);
            unsigned long long k3 = ((unsigned long long)__float_as_uint(f.w) << 32) | (unsigned)(basej + i * 4 + 3);
            keys[basej + i * 4 + 0] = k0;
            keys[basej + i * 4 + 1] = k1;
            keys[basej + i * 4 + 2] = k2;
            keys[basej + i * 4 + 3] = k3;
            mn = u64min(mn, u64min(u64min(k0, k1), u64min(k2, k3)));
        }
        segmin[seg] = mn;
    }
    __syncthreads();

    for (int k = 0; k < KN; k++) {
        unsigned long long m = u64min(segmin[tid], segmin[tid + 128]);
        #pragma unroll
        for (int o = 16; o; o >>= 1) {
            unsigned long long v = __shfl_xor_sync(0xffffffffu, m, o);
            m = u64min(m, v);
        }
        if ((tid & 31) == 0) red[tid >> 5] = m;
        __syncthreads();
        if (tid == 0) {
            m = u64min(u64min(red[0], red[1]), u64min(red[2], red[3]));
            int j = (int)(unsigned)(m & 0xffffffffULL);
            idxo[q * KN + k] = j;
            keys[j] = ~0ull;
            s_ext = j;
        }
        __syncthreads();
        if (k < KN - 1) {
            int seg = s_ext >> 4;
            if (tid < 16) {
                unsigned long long v = keys[seg * 16 + tid];
                #pragma unroll
                for (int o = 8; o; o >>= 1) {
                    unsigned long long w = __shfl_xor_sync(0xffffu, v, o);
                    v = u64min(v, w);
                }
                if (tid == 0) segmin[seg] = v;
            }
            __syncthreads();
        }
    }
}

// ---------------- fused MLP: 8x8 register-tiled block GEMM (FFMA2 packed) ----------------
#define TNP 8
#define AW 132
#define OFF_W    0
#define OFF_A    (131 * AW)
#define OFF_B    (OFF_A + 131 * AW)
#define OFF_H2   (OFF_B + 128 * AW)
#define OFF_SW2  (OFF_H2 + 128 * 8)
#define OFF_SB2  (OFF_SW2 + 128 * 8)
#define OFF_PS   (OFF_SB2 + 128)
#define OFF_IDX  (OFF_PS + 16 * 128)
#define MLP_SMEM ((OFF_IDX + 128) * 4)

template<int KIN>
__device__ __forceinline__ void mm8x8p(const float* __restrict__ A, const float* __restrict__ W,
                                       int tx, int ty, unsigned long long (&acc)[8][4])
{
    #pragma unroll 4
    for (int kk = 0; kk < KIN; kk++) {
        ulonglong2 a01 = *(const ulonglong2*)(A + kk * AW + tx * 8);
        ulonglong2 a23 = *(const ulonglong2*)(A + kk * AW + tx * 8 + 4);
        float4 w0 = *(const float4*)(W + kk * AW + ty * 8);
        float4 w1 = *(const float4*)(W + kk * AW + ty * 8 + 4);
        unsigned long long av[4] = {a01.x, a01.y, a23.x, a23.y};
        unsigned long long wb[8];
        wb[0] = bcast2(w0.x); wb[1] = bcast2(w0.y); wb[2] = bcast2(w0.z); wb[3] = bcast2(w0.w);
        wb[4] = bcast2(w1.x); wb[5] = bcast2(w1.y); wb[6] = bcast2(w1.z); wb[7] = bcast2(w1.w);
        #pragma unroll
        for (int u = 0; u < 8; u++)
            #pragma unroll
            for (int vp = 0; vp < 4; vp++)
                acc[u][vp] = fma2(wb[u], av[vp], acc[u][vp]);
    }
}

__device__ __forceinline__ void store_leaky8(float* dst, const unsigned long long (&acc)[8][4],
                                             int u)
{
    float x[8];
    unp2(acc[u][0], x[0], x[1]);
    unp2(acc[u][1], x[2], x[3]);
    unp2(acc[u][2], x[4], x[5]);
    unp2(acc[u][3], x[6], x[7]);
    float4 o0, o1;
    o0.x = leakyf(x[0]); o0.y = leakyf(x[1]); o0.z = leakyf(x[2]); o0.w = leakyf(x[3]);
    o1.x = leakyf(x[4]); o1.y = leakyf(x[5]); o1.z = leakyf(x[6]); o1.w = leakyf(x[7]);
    *(float4*)dst = o0;
    *(float4*)(dst + 4) = o1;
}

__global__ void __launch_bounds__(256) k_mlp(
    const float* __restrict__ w0g, const float* __restrict__ b0g,
    const float* __restrict__ w1g, const float* __restrict__ b1g,
    const float* __restrict__ w2g, const float* __restrict__ b2g,
    const float* __restrict__ n1w0, const float* __restrict__ n1b0,
    const float* __restrict__ n1w1, const float* __restrict__ n1b1,
    const float* __restrict__ n1w2, const float* __restrict__ n1b2)
{
    extern __shared__ float sm[];
    float* Wsm = sm + OFF_W;
    float* Abuf = sm + OFF_A;
    float* Bbuf = sm + OFF_B;
    float* h2s = sm + OFF_H2;
    float* sw2 = sm + OFF_SW2;
    float* sb2 = sm + OFF_SB2;
    float* ps  = sm + OFF_PS;
    int* idxs = (int*)(sm + OFF_IDX);

    int tid = threadIdx.x;
    int tx = tid & 15, ty = tid >> 4;
    int base = blockIdx.x * TNP;

    if (tid < 128) {
        idxs[tid] = g_idx1[base * KN + tid];
        #pragma unroll
        for (int r = 0; r < 8; r++) sw2[tid + 128 * r] = n1w2[tid + 128 * r];
        sb2[tid] = n1b2[tid];
    }
    __syncthreads();

    // stage A [131][128]
    for (int e = tid; e < 131 * 128; e += 256) {
        int i = e >> 7, col = e & 127;
        int tn = col >> 4;
        int pt = base + tn;
        int b = pt >> 12;
        int j = idxs[col];
        float v;
        if (i < 64) v = g_p1T[(size_t)pt * DD + i];
        else if (i < 128) v = g_p2T[((size_t)b * N2 + j) * DD + (i - 64)];
        else v = g_x2T[(b * N2 + j) * 3 + (i - 128)] - g_x1T[pt * 3 + (i - 128)];
        Abuf[i * AW + col] = v;
    }
    // stage W0 transposed [in 131][out 128]
    for (int e = tid; e < 128 * 131; e += 256) {
        int i = e % 131, c = e / 131;
        Wsm[i * AW + c] = w0g[e];
    }
    __syncthreads();

    // weight-net 1 (3->8->8) per column -> h2s[col][8]
    if (tid < 128) {
        int col = tid;
        float dx0 = Abuf[128 * AW + col];
        float dx1 = Abuf[129 * AW + col];
        float dx2 = Abuf[130 * AW + col];
        float h[8];
        #pragma unroll
        for (int j = 0; j < 8; j++) {
            float s = n1w0[j * 3 + 0] * dx0 + n1w0[j * 3 + 1] * dx1 + n1w0[j * 3 + 2] * dx2 + n1b0[j];
            h[j] = fmaxf(s, 0.f);
        }
        #pragma unroll
        for (int j = 0; j < 8; j++) {
            float s = n1b1[j];
            #pragma unroll
            for (int m = 0; m < 8; m++) s += n1w1[j * 8 + m] * h[m];
            h2s[col * 8 + j] = fmaxf(s, 0.f);
        }
    }
    __syncthreads();

    unsigned long long bias0[8], bias1[8], bias2[8];
    #pragma unroll
    for (int u = 0; u < 8; u++) {
        bias0[u] = bcast2(b0g[ty * 8 + u]);
        bias1[u] = bcast2(b1g[ty * 8 + u]);
        bias2[u] = bcast2(b2g[ty * 8 + u]);
    }

    unsigned long long acc[8][4];

    // ---- layer 1: 131 -> 128, leaky ----
    #pragma unroll
    for (int u = 0; u < 8; u++)
        #pragma unroll
        for (int vp = 0; vp < 4; vp++) acc[u][vp] = bias0[u];
    mm8x8p<131>(Abuf, Wsm, tx, ty, acc);
    #pragma unroll
    for (int u = 0; u < 8; u++)
        store_leaky8(Bbuf + (ty * 8 + u) * AW + tx * 8, acc, u);
    __syncthreads();

    // stage W1
    for (int e = tid; e < 128 * 128; e += 256) {
        int i = e & 127, c = e >> 7;
        Wsm[i * AW + c] = w1g[e];
    }
    __syncthreads();

    // ---- layer 2: 128 -> 128, leaky ----
    #pragma unroll
    for (int u = 0; u < 8; u++)
        #pragma unroll
        for (int vp = 0; vp < 4; vp++) acc[u][vp] = bias1[u];
    mm8x8p<128>(Bbuf, Wsm, tx, ty, acc);
    #pragma unroll
    for (int u = 0; u < 8; u++)
        store_leaky8(Abuf + (ty * 8 + u) * AW + tx * 8, acc, u);
    __syncthreads();

    // stage W2
    for (int e = tid; e < 128 * 128; e += 256) {
        int i = e & 127, c = e >> 7;
        Wsm[i * AW + c] = w2g[e];
    }
    __syncthreads();

    // ---- S matrix -> Bbuf ----
    {
        int col = tid >> 1, chalf = tid & 1;
        float hj[8];
        #pragma unroll
        for (int j = 0; j < 8; j++) hj[j] = h2s[col * 8 + j];
        #pragma unroll 4
        for (int cc = 0; cc < 64; cc++) {
            int c = chalf * 64 + cc;
            float s = sb2[c];
            #pragma unroll
            for (int j = 0; j < 8; j++) s += sw2[c * 8 + j] * hj[j];
            Bbuf[col * AW + c] = fmaxf(s, 0.f);
        }
    }

    // ---- layer 3: 128 -> 128 ----
    #pragma unroll
    for (int u = 0; u < 8; u++)
        #pragma unroll
        for (int vp = 0; vp < 4; vp++) acc[u][vp] = bias2[u];
    mm8x8p<128>(Abuf, Wsm, tx, ty, acc);
    __syncthreads();   // S writes visible

    // ---- epilogue ----
    {
        float partial[8];
        #pragma unroll
        for (int u = 0; u < 8; u++) partial[u] = 0.f;
        #pragma unroll
        for (int vp = 0; vp < 4; vp++) {
            float e0[8], e1[8];
            #pragma unroll
            for (int u = 0; u < 8; u++) unp2(acc[u][vp], e0[u], e1[u]);
            {
                int col = tx * 8 + 2 * vp;
                float4 s0 = *(const float4*)(Bbuf + col * AW + ty * 8);
                float4 s1 = *(const float4*)(Bbuf + col * AW + ty * 8 + 4);
                float s[8] = {s0.x, s0.y, s0.z, s0.w, s1.x, s1.y, s1.z, s1.w};
                #pragma unroll
                for (int u = 0; u < 8; u++) partial[u] += s[u] * leakyf(e0[u]);
            }
            {
                int col = tx * 8 + 2 * vp + 1;
                float4 s0 = *(const float4*)(Bbuf + col * AW + ty * 8);
                float4 s1 = *(const float4*)(Bbuf + col * AW + ty * 8 + 4);
                float s[8] = {s0.x, s0.y, s0.z, s0.w, s1.x, s1.y, s1.z, s1.w};
                #pragma unroll
                for (int u = 0; u < 8; u++) partial[u] += s[u] * leakyf(e1[u]);
            }
        }
        #pragma unroll
        for (int u = 0; u < 8; u++) ps[tx * 128 + ty * 8 + u] = partial[u];
    }
    __syncthreads();
    for (int e = tid; e < 1024; e += 256) {
        int tn = e >> 7, c = e & 127;
        g_p2p[(size_t)(base + tn) * CO + c] = ps[(2 * tn) * 128 + c] + ps[(2 * tn + 1) * 128 + c];
    }
}

// ---------------- patch aggregation ----------------
__global__ void __launch_bounds__(128) k_patch(
    const float* __restrict__ n2w0, const float* __restrict__ n2b0,
    const float* __restrict__ n2w1, const float* __restrict__ n2b1,
    const float* __restrict__ n2w2, const float* __restrict__ n2b2,
    float* __restrict__ out)
{
    __shared__ float h2s[16][8];
    __shared__ int js[16];
    int q = blockIdx.x;
    int b = q / N1, n = q % N1;
    int tid = threadIdx.x;
    if (tid < 16) {
        int j = g_idx2[q * KN + tid];
        js[tid] = j;
        float dx0 = g_x1T[(b * N1 + j) * 3 + 0] - g_x1T[q * 3 + 0];
        float dx1 = g_x1T[(b * N1 + j) * 3 + 1] - g_x1T[q * 3 + 1];
        float dx2 = g_x1T[(b * N1 + j) * 3 + 2] - g_x1T[q * 3 + 2];
        float h[8];
        #pragma unroll
        for (int jj = 0; jj < 8; jj++) {
            float s = n2w0[jj * 3 + 0] * dx0 + n2w0[jj * 3 + 1] * dx1 + n2w0[jj * 3 + 2] * dx2 + n2b0[jj];
            h[jj] = fmaxf(s, 0.f);
        }
        #pragma unroll
        for (int jj = 0; jj < 8; jj++) {
            float s = n2b1[jj];
            #pragma unroll
            for (int m = 0; m < 8; m++) s += n2w1[jj * 8 + m] * h[m];
            h2s[tid][jj] = fmaxf(s, 0.f);
        }
    }
    __syncthreads();
    int c = tid;
    float w2r[8];
    #pragma unroll
    for (int j = 0; j < 8; j++) w2r[j] = n2w2[c * 8 + j];
    float bc = n2b2[c];
    float acc = 0.f;
    #pragma unroll
    for (int k = 0; k < KN; k++) {
        float s = bc;
        #pragma unroll
        for (int j = 0; j < 8; j++) s += w2r[j] * h2s[k][j];
        s = fmaxf(s, 0.f);
        acc += s * g_p2p[((size_t)b * N1 + js[k]) * CO + c];
    }
    out[(size_t)b * CO * N1 + (size_t)c * N1 + n] = acc;
}

// ---------------- launch ----------------
extern "C" void kernel_launch(void* const* d_in, const int* in_sizes, int n_in,
                              void* d_out, int out_size)
{
    int s = (n_in >= 31) ? 0 : -2;
    const float* xyz1 = (const float*)d_in[0];
    const float* xyz2 = (const float*)d_in[1];
    const float* pts1 = (const float*)d_in[2];
    const float* pts2 = (const float*)d_in[3];
    const float* vel1 = (const float*)d_in[4];
    const float* fcc  = (const float*)d_in[8 + s];
    const float* fcv  = (const float*)d_in[9 + s];
    const float* wxyz = (const float*)d_in[10 + s];
    const float* wpts = (const float*)d_in[12 + s];
    const float* mw0 = (const float*)d_in[13 + s];
    const float* mb0 = (const float*)d_in[14 + s];
    const float* mw1 = (const float*)d_in[15 + s];
    const float* mb1 = (const float*)d_in[16 + s];
    const float* mw2 = (const float*)d_in[17 + s];
    const float* mb2 = (const float*)d_in[18 + s];
    const float* n1w0 = (const float*)d_in[19 + s];
    const float* n1b0 = (const float*)d_in[20 + s];
    const float* n2w0 = (const float*)d_in[21 + s];
    const float* n2b0 = (const float*)d_in[22 + s];
    const float* n1w1 = (const float*)d_in[23 + s];
    const float* n1b1 = (const float*)d_in[24 + s];
    const float* n2w1 = (const float*)d_in[25 + s];
    const float* n2b1 = (const float*)d_in[26 + s];
    const float* n1w2 = (const float*)d_in[27 + s];
    const float* n1b2 = (const float*)d_in[28 + s];
    const float* n2w2 = (const float*)d_in[29 + s];
    const float* n2b2 = (const float*)d_in[30 + s];

    float* out = (float*)d_out;
    const int patch_elems = BATCH * CO * N1;
    const int vw_elems = BATCH * N1 * 3;
    float* out_vw = (out_size >= patch_elems + vw_elems) ? (out + patch_elems) : nullptr;

    cudaFuncSetAttribute(k_mlp, cudaFuncAttributeMaxDynamicSharedMemorySize, (int)MLP_SMEM);
    cudaFuncSetAttribute(k_dist_tc, cudaFuncAttributeMaxDynamicSharedMemorySize, (int)DIST_SMEM);

    const int prep_total = 2 * BATCH * CP * N1 + 2 * BATCH * 3 * N1;
    dim3 gg(N2 / 128, N1 / 128, BATCH);
    dim3 gt(N1 / 32, 2 * BATCH * 2);

    // same ordering as round 6: capture lands on k_dist_tc
    k_rigid<<<(BATCH * N1 + 127) / 128, 128>>>(xyz1, vel1, fcc, fcv, out_vw);
    k_prep<<<(prep_total + 255) / 256, 256>>>(xyz1, xyz2, pts1, pts2, wxyz, wpts);
    k_norms<<<(BATCH * 4096 + 127) / 128, 128>>>();
    k_dist_tc<<<gg, 256, DIST_SMEM>>>(0);
    k_topk<<<BATCH * N1, 128>>>(0);
    k_transp<<<gt, 256>>>(pts1, pts2);
    k_mlp<<<(BATCH * N1) / TNP, 256, MLP_SMEM>>>(mw0, mb0, mw1, mb1, mw2, mb2,
                                                 n1w0, n1b0, n1w1, n1b1, n1w2, n1b2);
    k_comb<<<(BATCH * CP * N1 + 255) / 256, 256>>>();
    k_dist_tc<<<gg, 256, DIST_SMEM>>>(1);
    k_topk<<<BATCH * N1, 128>>>(1);
    k_patch<<<BATCH * N1, 128>>>(n2w0, n2b0, n2w1, n2b1, n2w2, n2b2, out);
}

// round 8
// speedup vs baseline: 1.1351x; 1.0141x over previous
#include <cuda_runtime.h>
#include <math.h>

#define BATCH 2
#define N1 4096
#define N2 4096
#define DD 64
#define KN 16
#define KCC 8
#define CP 80      // padded feature channels (67 / 70 used)
#define CO 128

// ---------------- scratch (static device memory; no runtime alloc) ----------------
__device__ float g_dist[(size_t)BATCH * N1 * N2];        // 134 MB
__device__ float g_F1[BATCH * CP * N1];
__device__ float g_F2[BATCH * CP * N2];
__device__ float g_CB[BATCH * CP * N1];
__device__ float g_nA[BATCH * N1];
__device__ float g_nB[BATCH * N2];
__device__ float g_nC[BATCH * N1];
__device__ int   g_idx1[BATCH * N1 * KN];
__device__ int   g_idx2[BATCH * N1 * KN];
__device__ float g_vw[BATCH * N1 * 3];
__device__ float g_wf[BATCH * N1];
__device__ float g_wr[BATCH * N1];
__device__ float g_p1T[BATCH * N1 * DD];
__device__ float g_p2T[BATCH * N2 * DD];
__device__ float g_x1T[BATCH * N1 * 3];
__device__ float g_x2T[BATCH * N2 * 3];
__device__ float g_p2p[(size_t)BATCH * N1 * CO];
__device__ float2 g_wT[3][136][128];    // hi/lo-split, transposed MLP weights

__device__ __forceinline__ float leakyf(float x) { return x >= 0.f ? x : 0.1f * x; }
__device__ __forceinline__ unsigned long long u64min(unsigned long long a, unsigned long long b) {
    return a < b ? a : b;
}

// ---- tf32 helpers ----
__device__ __forceinline__ float f2tf32f(float x) {
    unsigned int r;
    asm("cvt.rna.tf32.f32 %0, %1;" : "=r"(r) : "f"(x));
    return __uint_as_float(r);
}

#define MMA_TF32(acc, A0, A1, A2, A3, B0, B1)                                   \
    asm volatile("mma.sync.aligned.m16n8k8.row.col.f32.tf32.tf32.f32 "          \
                 "{%0,%1,%2,%3}, {%4,%5,%6,%7}, {%8,%9}, {%0,%1,%2,%3};"        \
                 : "+f"(acc[0]), "+f"(acc[1]), "+f"(acc[2]), "+f"(acc[3])       \
                 : "r"(__float_as_uint(A0)), "r"(__float_as_uint(A1)),          \
                   "r"(__float_as_uint(A2)), "r"(__float_as_uint(A3)),          \
                   "r"(__float_as_uint(B0)), "r"(__float_as_uint(B1)))

// ---------------- rigid 3x3 least squares + mask ----------------
__global__ void k_rigid(const float* __restrict__ xyz1, const float* __restrict__ vel1,
                        const float* __restrict__ fcc, const float* __restrict__ fcv,
                        float* __restrict__ out_vw)
{
    int t = blockIdx.x * blockDim.x + threadIdx.x;
    if (t >= BATCH * N1) return;
    int b = t / N1, n = t % N1;
    const float* cc = fcc + (size_t)t * KCC * 3;
    const float* cv = fcv + (size_t)t * KCC;
    double A00 = 1e-6, A01 = 0, A02 = 0, A11 = 1e-6, A12 = 0, A22 = 1e-6;
    double r0 = 0, r1 = 0, r2 = 0;
    for (int k = 0; k < KCC; k++) {
        double x = cc[k * 3 + 0], y = cc[k * 3 + 1], z = cc[k * 3 + 2];
        double inv = 1.0 / sqrt(x * x + y * y + z * z);
        x *= inv; y *= inv; z *= inv;
        A00 += x * x; A01 += x * y; A02 += x * z;
        A11 += y * y; A12 += y * z; A22 += z * z;
        double v = (double)cv[k];
        r0 += x * v; r1 += y * v; r2 += z * v;
    }
    double c00 = A11 * A22 - A12 * A12;
    double c01 = A01 * A22 - A12 * A02;
    double c02 = A01 * A12 - A11 * A02;
    double det = A00 * c00 - A01 * c01 + A02 * c02;
    double id = 1.0 / det;
    double v0 = (r0 * c00 - A01 * (r1 * A22 - A12 * r2) + A02 * (r1 * A12 - A11 * r2)) * id;
    double v1 = (A00 * (r1 * A22 - A12 * r2) - r0 * c01 + A02 * (A01 * r2 - r1 * A02)) * id;
    double v2 = (A00 * (A11 * r2 - r1 * A12) - A01 * (A01 * r2 - r1 * A02) + r0 * c02) * id;

    float fx = xyz1[(b * 3 + 0) * N1 + n];
    float fy = xyz1[(b * 3 + 1) * N1 + n];
    float fz = xyz1[(b * 3 + 2) * N1 + n];
    double inl = 1.0 / sqrt((double)fx * fx + (double)fy * fy + (double)fz * fz);
    double err = fabs((v0 * fx + v1 * fy + v2 * fz) * inl - (double)vel1[t]);
    bool m = (err <= 5.0);
    g_wf[t] = m ? 0.1f : 0.9f;
    g_wr[t] = m ? 0.9f : 0.1f;
    g_vw[t * 3 + 0] = (float)v0;
    g_vw[t * 3 + 1] = (float)v1;
    g_vw[t * 3 + 2] = (float)v2;
    if (out_vw) {
        out_vw[t * 3 + 0] = (float)v0;
        out_vw[t * 3 + 1] = (float)v1;
        out_vw[t * 3 + 2] = (float)v2;
    }
}

// ---------------- fused: weighted feature build + xyz transposes ----------------
__global__ void k_prep(const float* __restrict__ xyz1, const float* __restrict__ xyz2,
                       const float* __restrict__ pts1, const float* __restrict__ pts2,
                       const float* __restrict__ wxyz_p, const float* __restrict__ wpts_p)
{
    float wx = *wxyz_p, wp = *wpts_p;
    const int totalF = BATCH * CP * N1;
    const int tx3 = BATCH * 3 * N1;
    const int total = 2 * totalF + 2 * tx3;
    for (int e = blockIdx.x * blockDim.x + threadIdx.x; e < total;
         e += gridDim.x * blockDim.x) {
        if (e < 2 * totalF) {
            int which = e / totalF;
            int r = e % totalF;
            int b = r / (CP * N1);
            int c = (r / N1) % CP;
            int n = r % N1;
            const float* xyz = which ? xyz2 : xyz1;
            const float* pts = which ? pts2 : pts1;
            float* F = which ? g_F2 : g_F1;
            float v = 0.f;
            if (c < 3) v = wx * xyz[(b * 3 + c) * N1 + n];
            else if (c < 67) v = wp * pts[(b * DD + (c - 3)) * N1 + n];
            F[r] = v;
        } else {
            int r = e - 2 * totalF;
            if (r < tx3) {
                int b = r / (3 * N1), c = (r / N1) % 3, n = r % N1;
                g_x1T[(b * N1 + n) * 3 + c] = xyz1[r];
            } else {
                r -= tx3;
                int b = r / (3 * N1), c = (r / N1) % 3, n = r % N1;
                g_x2T[(b * N2 + n) * 3 + c] = xyz2[r];
            }
        }
    }
}

// ---------------- MLP weight transpose + tf32 hi/lo split (runs once) ----------------
__global__ void k_wprep(const float* __restrict__ w0, const float* __restrict__ w1,
                        const float* __restrict__ w2)
{
    const int per = 136 * 128;
    for (int e = blockIdx.x * blockDim.x + threadIdx.x; e < 3 * per;
         e += gridDim.x * blockDim.x) {
        int l = e / per;
        int r = e % per;
        int k = r >> 7, c = r & 127;
        int KD = (l == 0) ? 131 : 128;
        const float* w = (l == 0) ? w0 : (l == 1) ? w1 : w2;
        float v = (k < KD) ? w[c * KD + k] : 0.f;
        float h = f2tf32f(v);
        g_wT[l][k][c] = make_float2(h, f2tf32f(v - h));
    }
}

// ---------------- coalesced tiled transpose: [B][C][N] -> [B][N][C], C=64 ----------------
__global__ void __launch_bounds__(256) k_transp(const float* __restrict__ src1,
                                                const float* __restrict__ src2)
{
    __shared__ float t[32][33];
    int zc = blockIdx.y;
    int ct = zc & 1;
    int b = (zc >> 1) & (BATCH - 1);
    int which = zc >> 2;
    const float* src = which ? src2 : src1;
    float* dst = which ? g_p2T : g_p1T;
    int n0 = blockIdx.x * 32;
    int c0 = ct * 32;
    int lx = threadIdx.x & 31, ly = threadIdx.x >> 5;
    #pragma unroll
    for (int r = 0; r < 4; r++) {
        int c = c0 + ly + r * 8;
        t[ly + r * 8][lx] = src[((size_t)b * DD + c) * N1 + n0 + lx];
    }
    __syncthreads();
    #pragma unroll
    for (int r = 0; r < 4; r++) {
        int n = n0 + ly + r * 8;
        dst[((size_t)b * N1 + n) * DD + c0 + lx] = t[lx][ly + r * 8];
    }
}

// ---------------- all three squared norms in one launch ----------------
__global__ void k_norms()
{
    int t = blockIdx.x * blockDim.x + threadIdx.x;
    if (t >= BATCH * 4096) return;
    int b = t / 4096, n = t % 4096;
    float sA = 0.f, sB = 0.f;
    #pragma unroll 8
    for (int c = 0; c < CP; c++) {
        float a = g_F1[(b * CP + c) * 4096 + n];
        float bb = g_F2[(b * CP + c) * 4096 + n];
        sA += a * a;
        sB += bb * bb;
    }
    g_nA[t] = sA;
    g_nB[t] = sB;
    float wf = g_wf[t], wr = g_wr[t];
    float v0 = g_vw[t * 3 + 0], v1 = g_vw[t * 3 + 1], v2 = g_vw[t * 3 + 2];
    g_nC[t] = wf * wf * sA + wr * wr * (v0 * v0 + v1 * v1 + v2 * v2);
}

// ---------------- comb features for second KNN ----------------
__global__ void k_comb()
{
    const int total = BATCH * CP * N1;
    for (int e = blockIdx.x * blockDim.x + threadIdx.x; e < total;
         e += gridDim.x * blockDim.x) {
        int b = e / (CP * N1);
        int c = (e / N1) % CP;
        int n = e % N1;
        float v = 0.f;
        if (c < 67) v = g_wf[b * N1 + n] * g_F1[e];
        else if (c < 70) v = g_wr[b * N1 + n] * g_vw[(b * N1 + n) * 3 + (c - 67)];
        g_CB[e] = v;
    }
}

// ---------------- distance GEMM on tensor cores (3xTF32, hi/lo interleaved) ----------------
#define CPK 40
#define S2 132
#define SLAB2 (CPK * S2)
#define DIST_SMEM ((2 * SLAB2 * 2 + 256) * 4)

__global__ void __launch_bounds__(256) k_dist_tc(int sel)
{
    extern __shared__ float2 dsm2[];
    float2* As2 = dsm2;                 // [CPK][S2] (hi,lo)
    float2* Bs2 = As2 + SLAB2;
    float* nAs = (float*)(Bs2 + SLAB2); // 128
    float* nBs = nAs + 128;             // 128

    const float* FA = sel ? g_CB : g_F1;
    const float* FB = sel ? g_CB : g_F2;
    const float* nAv = sel ? g_nC : g_nA;
    const float* nBv = sel ? g_nC : g_nB;

    int b = blockIdx.z;
    int i0 = blockIdx.y * 128, j0 = blockIdx.x * 128;
    const float* Asrc = FA + (size_t)b * CP * N1 + i0;
    const float* Bsrc = FB + (size_t)b * CP * N2 + j0;

    int tid = threadIdx.x;
    if (tid < 128) {
        nAs[tid] = nAv[b * N1 + i0 + tid];
        nBs[tid] = nBv[b * N2 + j0 + tid];
    }

    int warp = tid >> 5, lane = tid & 31;
    int gid = lane >> 2, tig = lane & 3;
    int mi = warp * 16 + gid;

    float acc[16][4];
    #pragma unroll
    for (int nt = 0; nt < 16; nt++)
        #pragma unroll
        for (int u = 0; u < 4; u++) acc[nt][u] = 0.f;

    for (int kb = 0; kb < CP; kb += CPK) {
        for (int idx = tid; idx < CPK * 32 * 2; idx += 256) {
            int which = idx >= CPK * 32;
            int r = which ? idx - CPK * 32 : idx;
            int k = r >> 5, c4 = (r & 31) << 2;
            const float* src = which ? Bsrc : Asrc;
            float2* dst = (which ? Bs2 : As2) + k * S2 + c4;
            float4 v = *(const float4*)(src + (size_t)(kb + k) * 4096 + c4);
            float h;
            h = f2tf32f(v.x); dst[0] = make_float2(h, f2tf32f(v.x - h));
            h = f2tf32f(v.y); dst[1] = make_float2(h, f2tf32f(v.y - h));
            h = f2tf32f(v.z); dst[2] = make_float2(h, f2tf32f(v.z - h));
            h = f2tf32f(v.w); dst[3] = make_float2(h, f2tf32f(v.w - h));
        }
        __syncthreads();

        #pragma unroll
        for (int kk = 0; kk < CPK; kk += 8) {
            const float2* r0 = As2 + (kk + tig) * S2;
            const float2* r1 = As2 + (kk + tig + 4) * S2;
            float2 a0 = r0[mi], a1 = r0[mi + 8];
            float2 a2 = r1[mi], a3 = r1[mi + 8];
            const float2* q0 = Bs2 + (kk + tig) * S2;
            const float2* q1 = Bs2 + (kk + tig + 4) * S2;
            #pragma unroll
            for (int nt = 0; nt < 16; nt++) {
                int nb = nt * 8 + gid;
                float2 b0 = q0[nb], b1 = q1[nb];
                MMA_TF32(acc[nt], a0.y, a1.y, a2.y, a3.y, b0.x, b1.x);  // lo*hi
                MMA_TF32(acc[nt], a0.x, a1.x, a2.x, a3.x, b0.y, b1.y);  // hi*lo
                MMA_TF32(acc[nt], a0.x, a1.x, a2.x, a3.x, b0.x, b1.x);  // hi*hi
            }
        }
        __syncthreads();
    }

    float* drow = g_dist + (size_t)b * N1 * N2;
    float ni0 = nAs[mi], ni1 = nAs[mi + 8];
    size_t ro0 = (size_t)(i0 + mi) * N2 + j0;
    size_t ro1 = ro0 + (size_t)8 * N2;
    #pragma unroll
    for (int nt = 0; nt < 16; nt++) {
        int jc = nt * 8 + tig * 2;
        float nj0 = nBs[jc], nj1 = nBs[jc + 1];
        float2 o0, o1;
        o0.x = fmaxf(ni0 - 2.f * acc[nt][0] + nj0, 0.f);
        o0.y = fmaxf(ni0 - 2.f * acc[nt][1] + nj1, 0.f);
        o1.x = fmaxf(ni1 - 2.f * acc[nt][2] + nj0, 0.f);
        o1.y = fmaxf(ni1 - 2.f * acc[nt][3] + nj1, 0.f);
        *(float2*)(drow + ro0 + jc) = o0;
        *(float2*)(drow + ro1 + jc) = o1;
    }
}

// ---------------- top-K via incremental segment-min selection ----------------
__global__ void __launch_bounds__(128) k_topk(int sel)
{
    __shared__ unsigned long long keys[N2];
    __shared__ unsigned long long segmin[256];
    __shared__ unsigned long long red[4];
    __shared__ int s_ext;
    int q = blockIdx.x;
    const float* row = g_dist + (size_t)q * N2;
    int* idxo = sel ? g_idx2 : g_idx1;
    int tid = threadIdx.x;

    #pragma unroll
    for (int s2 = 0; s2 < 2; s2++) {
        int seg = tid * 2 + s2;
        int basej = seg * 16;
        unsigned long long mn = ~0ull;
        #pragma unroll
        for (int i = 0; i < 4; i++) {
            float4 f = *(const float4*)(row + basej + i * 4);
            unsigned long long k0 = ((unsigned long long)__float_as_uint(f.x) << 32) | (unsigned)(basej + i * 4 + 0);
            unsigned long long k1 = ((unsigned long long)__float_as_uint(f.y) << 32) | (unsigned)(basej + i * 4 + 1);
            unsigned long long k2 = ((unsigned long long)__float_as_uint(f.z) << 32) | (unsigned)(basej + i * 4 + 2);
            unsigned long long k3 = ((unsigned long long)__float_as_uint(f.w) << 32) | (unsigned)(basej + i * 4 + 3);
            keys[basej + i * 4 + 0] = k0;
            keys[basej + i * 4 + 1] = k1;
            keys[basej + i * 4 + 2] = k2;
            keys[basej + i * 4 + 3] = k3;
            mn = u64min(mn, u64min(u64min(k0, k1), u64min(k2, k3)));
        }
        segmin[seg] = mn;
    }
    __syncthreads();

    for (int k = 0; k < KN; k++) {
        unsigned long long m = u64min(segmin[tid], segmin[tid + 128]);
        #pragma unroll
        for (int o = 16; o; o >>= 1) {
            unsigned long long v = __shfl_xor_sync(0xffffffffu, m, o);
            m = u64min(m, v);
        }
        if ((tid & 31) == 0) red[tid >> 5] = m;
        __syncthreads();
        if (tid == 0) {
            m = u64min(u64min(red[0], red[1]), u64min(red[2], red[3]));
            int j = (int)(unsigned)(m & 0xffffffffULL);
            idxo[q * KN + k] = j;
            keys[j] = ~0ull;
            s_ext = j;
        }
        __syncthreads();
        if (k < KN - 1) {
            int seg = s_ext >> 4;
            if (tid < 16) {
                unsigned long long v = keys[seg * 16 + tid];
                #pragma unroll
                for (int o = 8; o; o >>= 1) {
                    unsigned long long w = __shfl_xor_sync(0xffffu, v, o);
                    v = u64min(v, w);
                }
                if (tid == 0) segmin[seg] = v;
            }
            __syncthreads();
        }
    }
}

// ---------------- fused MLP on tensor cores (3xTF32) ----------------
// 512 threads (16 warps), block = 8 points x 16 neighbors = 128 columns.
// M = columns (128), N = out channels (128), K = in channels (136/128 padded).
#define TNP 8
#define SY 132
#define MX   0                      // Xbuf [136][SY] fp32
#define MYO  (136 * SY)             // Ybuf [128][SY] fp32
#define MWC  (MYO + 128 * SY)       // Wc [32][SY] float2 (hi,lo)
#define MB   (MWC + 32 * SY * 2)    // biases [3][128]
#define MH2  (MB + 384)             // h2s [128][8]
#define MSW2 (MH2 + 1024)           // sw2 [128][8]
#define MSB2 (MSW2 + 1024)          // sb2 [128]
#define MIDX (MSB2 + 128)           // idxs [128]
#define MLP2_SMEM ((MIDX + 128) * 4)

__global__ void __launch_bounds__(512) k_mlp_tc(
    const float* __restrict__ b0g, const float* __restrict__ b1g,
    const float* __restrict__ b2g,
    const float* __restrict__ n1w0, const float* __restrict__ n1b0,
    const float* __restrict__ n1w1, const float* __restrict__ n1b1,
    const float* __restrict__ n1w2, const float* __restrict__ n1b2)
{
    extern __shared__ float sm[];
    float* Xbuf = sm + MX;
    float* Ybuf = sm + MYO;
    float2* Wc = (float2*)(sm + MWC);
    float* biasS = sm + MB;
    float* h2s = sm + MH2;
    float* sw2 = sm + MSW2;
    float* sb2 = sm + MSB2;
    int* idxs = (int*)(sm + MIDX);

    int tid = threadIdx.x;
    int warp = tid >> 5, lane = tid & 31;
    int gid = lane >> 2, tig = lane & 3;
    int wm = warp & 7, nh = warp >> 3;
    int mi = wm * 16 + gid;
    int base = blockIdx.x * TNP;

    if (tid < 128) {
        idxs[tid] = g_idx1[base * KN + tid];
        #pragma unroll
        for (int r = 0; r < 8; r++) sw2[tid + 128 * r] = n1w2[tid + 128 * r];
        sb2[tid] = n1b2[tid];
        biasS[tid] = b0g[tid];
        biasS[128 + tid] = b1g[tid];
        biasS[256 + tid] = b2g[tid];
    }
    __syncthreads();

    // stage Xbuf [136][128]: rows 0-63 p1, 64-127 gathered p2, 128-130 dxyz, 131-135 zero
    for (int e = tid; e < 136 * 128; e += 512) {
        int i = e >> 7, col = e & 127;
        int tn = col >> 4;
        int pt = base + tn;
        int b = pt >> 12;
        int j = idxs[col];
        float v;
        if (i < 64) v = g_p1T[(size_t)pt * DD + i];
        else if (i < 128) v = g_p2T[((size_t)b * N2 + j) * DD + (i - 64)];
        else if (i < 131) v = g_x2T[(b * N2 + j) * 3 + (i - 128)] - g_x1T[pt * 3 + (i - 128)];
        else v = 0.f;
        Xbuf[i * SY + col] = v;
    }
    __syncthreads();

    // weight-net 1 (3->8->8) per column -> h2s[col][8]
    if (tid < 128) {
        int col = tid;
        float dx0 = Xbuf[128 * SY + col];
        float dx1 = Xbuf[129 * SY + col];
        float dx2 = Xbuf[130 * SY + col];
        float h[8];
        #pragma unroll
        for (int j = 0; j < 8; j++) {
            float s = n1w0[j * 3 + 0] * dx0 + n1w0[j * 3 + 1] * dx1 + n1w0[j * 3 + 2] * dx2 + n1b0[j];
            h[j] = fmaxf(s, 0.f);
        }
        #pragma unroll
        for (int j = 0; j < 8; j++) {
            float s = n1b1[j];
            #pragma unroll
            for (int m = 0; m < 8; m++) s += n1w1[j * 8 + m] * h[m];
            h2s[col * 8 + j] = fmaxf(s, 0.f);
        }
    }

    // ---- three GEMM layers ----
    #pragma unroll 1
    for (int l = 0; l < 3; l++) {
        const int KL = (l == 0) ? 136 : 128;
        const float* Xin = (l == 1) ? Ybuf : Xbuf;
        float* Yout = (l == 1) ? Xbuf : Ybuf;

        float acc[8][4];
        #pragma unroll
        for (int nti = 0; nti < 8; nti++) {
            int c0 = (nh * 8 + nti) * 8 + tig * 2;
            acc[nti][0] = biasS[l * 128 + c0];
            acc[nti][1] = biasS[l * 128 + c0 + 1];
            acc[nti][2] = acc[nti][0];
            acc[nti][3] = acc[nti][1];
        }

        for (int k0 = 0; k0 < KL; k0 += 32) {
            int cs = (KL - k0 < 32) ? (KL - k0) : 32;
            __syncthreads();
            for (int e = tid; e < cs * 128; e += 512) {
                int kl = e >> 7, c = e & 127;
                Wc[kl * SY + c] = g_wT[l][k0 + kl][c];
            }
            __syncthreads();
            for (int kk = 0; kk < cs; kk += 8) {
                const float* xr0 = Xin + (k0 + kk + tig) * SY;
                const float* xr1 = Xin + (k0 + kk + tig + 4) * SY;
                float a0f = xr0[mi], a1f = xr0[mi + 8];
                float a2f = xr1[mi], a3f = xr1[mi + 8];
                float a0h = f2tf32f(a0f), a1h = f2tf32f(a1f);
                float a2h = f2tf32f(a2f), a3h = f2tf32f(a3f);
                float a0l = f2tf32f(a0f - a0h), a1l = f2tf32f(a1f - a1h);
                float a2l = f2tf32f(a2f - a2h), a3l = f2tf32f(a3f - a3h);
                const float2* w0p = Wc + (kk + tig) * SY;
                const float2* w1p = Wc + (kk + tig + 4) * SY;
                #pragma unroll
                for (int nti = 0; nti < 8; nti++) {
                    int nb = (nh * 8 + nti) * 8 + gid;
                    float2 b0 = w0p[nb], b1 = w1p[nb];
                    MMA_TF32(acc[nti], a0l, a1l, a2l, a3l, b0.x, b1.x);  // lo*hi
                    MMA_TF32(acc[nti], a0h, a1h, a2h, a3h, b0.y, b1.y);  // hi*lo
                    MMA_TF32(acc[nti], a0h, a1h, a2h, a3h, b0.x, b1.x);  // hi*hi
                }
            }
        }
        __syncthreads();
        // store with leaky into Yout[c][col]
        #pragma unroll
        for (int nti = 0; nti < 8; nti++) {
            int c0 = (nh * 8 + nti) * 8 + tig * 2;
            Yout[c0 * SY + mi] = leakyf(acc[nti][0]);
            Yout[(c0 + 1) * SY + mi] = leakyf(acc[nti][1]);
            Yout[c0 * SY + mi + 8] = leakyf(acc[nti][2]);
            Yout[(c0 + 1) * SY + mi + 8] = leakyf(acc[nti][3]);
        }
    }
    __syncthreads();
    // Y3 (leaky applied) is in Ybuf[c][col].

    // ---- S matrix into Xbuf[col][c] ----
    {
        int col = tid >> 2, cq = tid & 3;
        float hj[8];
        #pragma unroll
        for (int j = 0; j < 8; j++) hj[j] = h2s[col * 8 + j];
        #pragma unroll 4
        for (int cc = 0; cc < 32; cc++) {
            int c = cq * 32 + cc;
            float s = sb2[c];
            #pragma unroll
            for (int j = 0; j < 8; j++) s += sw2[c * 8 + j] * hj[j];
            Xbuf[col * SY + c] = fmaxf(s, 0.f);
        }
    }
    __syncthreads();

    // ---- p2p[pt][c] = sum_k S[pt*16+k][c] * Y3[c][pt*16+k] ----
    for (int e = tid; e < 1024; e += 512) {
        int pt = e >> 7, c = e & 127;
        const float* yr = Ybuf + c * SY + pt * 16;
        const float* sc = Xbuf + (pt * 16) * SY + c;
        float a = 0.f;
        #pragma unroll
        for (int k = 0; k < 16; k++) a += sc[k * SY] * yr[k];
        g_p2p[(size_t)(base + pt) * CO + c] = a;
    }
}

// ---------------- patch aggregation ----------------
__global__ void __launch_bounds__(128) k_patch(
    const float* __restrict__ n2w0, const float* __restrict__ n2b0,
    const float* __restrict__ n2w1, const float* __restrict__ n2b1,
    const float* __restrict__ n2w2, const float* __restrict__ n2b2,
    float* __restrict__ out)
{
    __shared__ float h2s[16][8];
    __shared__ int js[16];
    int q = blockIdx.x;
    int b = q / N1, n = q % N1;
    int tid = threadIdx.x;
    if (tid < 16) {
        int j = g_idx2[q * KN + tid];
        js[tid] = j;
        float dx0 = g_x1T[(b * N1 + j) * 3 + 0] - g_x1T[q * 3 + 0];
        float dx1 = g_x1T[(b * N1 + j) * 3 + 1] - g_x1T[q * 3 + 1];
        float dx2 = g_x1T[(b * N1 + j) * 3 + 2] - g_x1T[q * 3 + 2];
        float h[8];
        #pragma unroll
        for (int jj = 0; jj < 8; jj++) {
            float s = n2w0[jj * 3 + 0] * dx0 + n2w0[jj * 3 + 1] * dx1 + n2w0[jj * 3 + 2] * dx2 + n2b0[jj];
            h[jj] = fmaxf(s, 0.f);
        }
        #pragma unroll
        for (int jj = 0; jj < 8; jj++) {
            float s = n2b1[jj];
            #pragma unroll
            for (int m = 0; m < 8; m++) s += n2w1[jj * 8 + m] * h[m];
            h2s[tid][jj] = fmaxf(s, 0.f);
        }
    }
    __syncthreads();
    int c = tid;
    float w2r[8];
    #pragma unroll
    for (int j = 0; j < 8; j++) w2r[j] = n2w2[c * 8 + j];
    float bc = n2b2[c];
    float acc = 0.f;
    #pragma unroll
    for (int k = 0; k < KN; k++) {
        float s = bc;
        #pragma unroll
        for (int j = 0; j < 8; j++) s += w2r[j] * h2s[k][j];
        s = fmaxf(s, 0.f);
        acc += s * g_p2p[((size_t)b * N1 + js[k]) * CO + c];
    }
    out[(size_t)b * CO * N1 + (size_t)c * N1 + n] = acc;
}

// ---------------- launch ----------------
extern "C" void kernel_launch(void* const* d_in, const int* in_sizes, int n_in,
                              void* d_out, int out_size)
{
    int s = (n_in >= 31) ? 0 : -2;
    const float* xyz1 = (const float*)d_in[0];
    const float* xyz2 = (const float*)d_in[1];
    const float* pts1 = (const float*)d_in[2];
    const float* pts2 = (const float*)d_in[3];
    const float* vel1 = (const float*)d_in[4];
    const float* fcc  = (const float*)d_in[8 + s];
    const float* fcv  = (const float*)d_in[9 + s];
    const float* wxyz = (const float*)d_in[10 + s];
    const float* wpts = (const float*)d_in[12 + s];
    const float* mw0 = (const float*)d_in[13 + s];
    const float* mb0 = (const float*)d_in[14 + s];
    const float* mw1 = (const float*)d_in[15 + s];
    const float* mb1 = (const float*)d_in[16 + s];
    const float* mw2 = (const float*)d_in[17 + s];
    const float* mb2 = (const float*)d_in[18 + s];
    const float* n1w0 = (const float*)d_in[19 + s];
    const float* n1b0 = (const float*)d_in[20 + s];
    const float* n2w0 = (const float*)d_in[21 + s];
    const float* n2b0 = (const float*)d_in[22 + s];
    const float* n1w1 = (const float*)d_in[23 + s];
    const float* n1b1 = (const float*)d_in[24 + s];
    const float* n2w1 = (const float*)d_in[25 + s];
    const float* n2b1 = (const float*)d_in[26 + s];
    const float* n1w2 = (const float*)d_in[27 + s];
    const float* n1b2 = (const float*)d_in[28 + s];
    const float* n2w2 = (const float*)d_in[29 + s];
    const float* n2b2 = (const float*)d_in[30 + s];

    float* out = (float*)d_out;
    const int patch_elems = BATCH * CO * N1;
    const int vw_elems = BATCH * N1 * 3;
    float* out_vw = (out_size >= patch_elems + vw_elems) ? (out + patch_elems) : nullptr;

    cudaFuncSetAttribute(k_mlp_tc, cudaFuncAttributeMaxDynamicSharedMemorySize, (int)MLP2_SMEM);
    cudaFuncSetAttribute(k_dist_tc, cudaFuncAttributeMaxDynamicSharedMemorySize, (int)DIST_SMEM);

    const int prep_total = 2 * BATCH * CP * N1 + 2 * BATCH * 3 * N1;
    dim3 gg(N2 / 128, N1 / 128, BATCH);
    dim3 gt(N1 / 32, 2 * BATCH * 2);

    k_rigid<<<(BATCH * N1 + 127) / 128, 128>>>(xyz1, vel1, fcc, fcv, out_vw);
    k_prep<<<(prep_total + 255) / 256, 256>>>(xyz1, xyz2, pts1, pts2, wxyz, wpts);
    k_norms<<<(BATCH * 4096 + 127) / 128, 128>>>();
    k_dist_tc<<<gg, 256, DIST_SMEM>>>(0);          // 4th launch -> ncu lands here
    k_topk<<<BATCH * N1, 128>>>(0);
    k_transp<<<gt, 256>>>(pts1, pts2);
    k_wprep<<<204, 256>>>(mw0, mw1, mw2);
    k_mlp_tc<<<(BATCH * N1) / TNP, 512, MLP2_SMEM>>>(mb0, mb1, mb2,
                                                     n1w0, n1b0, n1w1, n1b1, n1w2, n1b2);
    k_comb<<<(BATCH * CP * N1 + 255) / 256, 256>>>();
    k_dist_tc<<<gg, 256, DIST_SMEM>>>(1);
    k_topk<<<BATCH * N1, 128>>>(1);
    k_patch<<<BATCH * N1, 128>>>(n2w0, n2b0, n2w1, n2b1, n2w2, n2b2, out);
}

// round 9
// speedup vs baseline: 1.3559x; 1.1945x over previous
#include <cuda_runtime.h>
#include <cuda_bf16.h>
#include <math.h>

#define BATCH 2
#define N1 4096
#define N2 4096
#define DD 64
#define KN 16
#define KCC 8
#define CP 80      // padded feature channels (67 / 70 used)
#define CO 128

// ---------------- scratch (static device memory; no runtime alloc) ----------------
__device__ float g_dist[(size_t)BATCH * N1 * N2];        // 134 MB
__device__ float g_F1[BATCH * CP * N1];
__device__ float g_F2[BATCH * CP * N2];
__device__ float g_CB[BATCH * CP * N1];
__device__ float g_nA[BATCH * N1];
__device__ float g_nB[BATCH * N2];
__device__ float g_nC[BATCH * N1];
__device__ int   g_idx1[BATCH * N1 * KN];
__device__ int   g_idx2[BATCH * N1 * KN];
__device__ float g_vw[BATCH * N1 * 3];
__device__ float g_wf[BATCH * N1];
__device__ float g_wr[BATCH * N1];
__device__ float g_p1T[BATCH * N1 * DD];
__device__ float g_p2T[BATCH * N2 * DD];
__device__ float g_x1T[BATCH * N1 * 3];
__device__ float g_x2T[BATCH * N2 * 3];
__device__ float g_p2p[(size_t)BATCH * N1 * CO];
__device__ uint2 g_wbf[3][72][128];     // bf16 hi/lo split, transposed MLP weights (k-pairs)

__device__ __forceinline__ float leakyf(float x) { return x >= 0.f ? x : 0.1f * x; }
__device__ __forceinline__ unsigned long long u64min(unsigned long long a, unsigned long long b) {
    return a < b ? a : b;
}

// ---- tf32 helpers (dist kernel) ----
__device__ __forceinline__ float f2tf32f(float x) {
    unsigned int r;
    asm("cvt.rna.tf32.f32 %0, %1;" : "=r"(r) : "f"(x));
    return __uint_as_float(r);
}

#define MMA_TF32(acc, A0, A1, A2, A3, B0, B1)                                   \
    asm volatile("mma.sync.aligned.m16n8k8.row.col.f32.tf32.tf32.f32 "          \
                 "{%0,%1,%2,%3}, {%4,%5,%6,%7}, {%8,%9}, {%0,%1,%2,%3};"        \
                 : "+f"(acc[0]), "+f"(acc[1]), "+f"(acc[2]), "+f"(acc[3])       \
                 : "r"(__float_as_uint(A0)), "r"(__float_as_uint(A1)),          \
                   "r"(__float_as_uint(A2)), "r"(__float_as_uint(A3)),          \
                   "r"(__float_as_uint(B0)), "r"(__float_as_uint(B1)))

// ---- bf16 helpers (mlp kernel) ----
__device__ __forceinline__ float bf16_trunc(float x) {          // exact split: top 16 bits
    return __uint_as_float(__float_as_uint(x) & 0xffff0000u);
}
__device__ __forceinline__ unsigned packbf2(float lo_elem, float hi_elem) {
    __nv_bfloat162 v = __floats2bfloat162_rn(lo_elem, hi_elem); // .x = first arg (low half)
    return *(unsigned*)&v;
}

#define MMA_BF16(acc, A0, A1, A2, A3, B0, B1)                                   \
    asm volatile("mma.sync.aligned.m16n8k16.row.col.f32.bf16.bf16.f32 "         \
                 "{%0,%1,%2,%3}, {%4,%5,%6,%7}, {%8,%9}, {%0,%1,%2,%3};"        \
                 : "+f"(acc[0]), "+f"(acc[1]), "+f"(acc[2]), "+f"(acc[3])       \
                 : "r"(A0), "r"(A1), "r"(A2), "r"(A3), "r"(B0), "r"(B1))

// ---------------- rigid 3x3 least squares + mask ----------------
__global__ void k_rigid(const float* __restrict__ xyz1, const float* __restrict__ vel1,
                        const float* __restrict__ fcc, const float* __restrict__ fcv,
                        float* __restrict__ out_vw)
{
    int t = blockIdx.x * blockDim.x + threadIdx.x;
    if (t >= BATCH * N1) return;
    int b = t / N1, n = t % N1;
    const float* cc = fcc + (size_t)t * KCC * 3;
    const float* cv = fcv + (size_t)t * KCC;
    double A00 = 1e-6, A01 = 0, A02 = 0, A11 = 1e-6, A12 = 0, A22 = 1e-6;
    double r0 = 0, r1 = 0, r2 = 0;
    for (int k = 0; k < KCC; k++) {
        double x = cc[k * 3 + 0], y = cc[k * 3 + 1], z = cc[k * 3 + 2];
        double inv = 1.0 / sqrt(x * x + y * y + z * z);
        x *= inv; y *= inv; z *= inv;
        A00 += x * x; A01 += x * y; A02 += x * z;
        A11 += y * y; A12 += y * z; A22 += z * z;
        double v = (double)cv[k];
        r0 += x * v; r1 += y * v; r2 += z * v;
    }
    double c00 = A11 * A22 - A12 * A12;
    double c01 = A01 * A22 - A12 * A02;
    double c02 = A01 * A12 - A11 * A02;
    double det = A00 * c00 - A01 * c01 + A02 * c02;
    double id = 1.0 / det;
    double v0 = (r0 * c00 - A01 * (r1 * A22 - A12 * r2) + A02 * (r1 * A12 - A11 * r2)) * id;
    double v1 = (A00 * (r1 * A22 - A12 * r2) - r0 * c01 + A02 * (A01 * r2 - r1 * A02)) * id;
    double v2 = (A00 * (A11 * r2 - r1 * A12) - A01 * (A01 * r2 - r1 * A02) + r0 * c02) * id;

    float fx = xyz1[(b * 3 + 0) * N1 + n];
    float fy = xyz1[(b * 3 + 1) * N1 + n];
    float fz = xyz1[(b * 3 + 2) * N1 + n];
    double inl = 1.0 / sqrt((double)fx * fx + (double)fy * fy + (double)fz * fz);
    double err = fabs((v0 * fx + v1 * fy + v2 * fz) * inl - (double)vel1[t]);
    bool m = (err <= 5.0);
    g_wf[t] = m ? 0.1f : 0.9f;
    g_wr[t] = m ? 0.9f : 0.1f;
    g_vw[t * 3 + 0] = (float)v0;
    g_vw[t * 3 + 1] = (float)v1;
    g_vw[t * 3 + 2] = (float)v2;
    if (out_vw) {
        out_vw[t * 3 + 0] = (float)v0;
        out_vw[t * 3 + 1] = (float)v1;
        out_vw[t * 3 + 2] = (float)v2;
    }
}

// ---------------- fused: weighted feature build + xyz transposes ----------------
__global__ void k_prep(const float* __restrict__ xyz1, const float* __restrict__ xyz2,
                       const float* __restrict__ pts1, const float* __restrict__ pts2,
                       const float* __restrict__ wxyz_p, const float* __restrict__ wpts_p)
{
    float wx = *wxyz_p, wp = *wpts_p;
    const int totalF = BATCH * CP * N1;
    const int tx3 = BATCH * 3 * N1;
    const int total = 2 * totalF + 2 * tx3;
    for (int e = blockIdx.x * blockDim.x + threadIdx.x; e < total;
         e += gridDim.x * blockDim.x) {
        if (e < 2 * totalF) {
            int which = e / totalF;
            int r = e % totalF;
            int b = r / (CP * N1);
            int c = (r / N1) % CP;
            int n = r % N1;
            const float* xyz = which ? xyz2 : xyz1;
            const float* pts = which ? pts2 : pts1;
            float* F = which ? g_F2 : g_F1;
            float v = 0.f;
            if (c < 3) v = wx * xyz[(b * 3 + c) * N1 + n];
            else if (c < 67) v = wp * pts[(b * DD + (c - 3)) * N1 + n];
            F[r] = v;
        } else {
            int r = e - 2 * totalF;
            if (r < tx3) {
                int b = r / (3 * N1), c = (r / N1) % 3, n = r % N1;
                g_x1T[(b * N1 + n) * 3 + c] = xyz1[r];
            } else {
                r -= tx3;
                int b = r / (3 * N1), c = (r / N1) % 3, n = r % N1;
                g_x2T[(b * N2 + n) * 3 + c] = xyz2[r];
            }
        }
    }
}

// ---------------- MLP weight transpose + bf16 hi/lo split (runs once) ----------------
__global__ void k_wprep(const float* __restrict__ w0, const float* __restrict__ w1,
                        const float* __restrict__ w2)
{
    const int per = 72 * 128;
    for (int e = blockIdx.x * blockDim.x + threadIdx.x; e < 3 * per;
         e += gridDim.x * blockDim.x) {
        int l = e / per;
        int r = e % per;
        int kp = r >> 7, c = r & 127;
        int KD = (l == 0) ? 131 : 128;
        const float* w = (l == 0) ? w0 : (l == 1) ? w1 : w2;
        int k0 = 2 * kp, k1 = 2 * kp + 1;
        float v0 = (k0 < KD) ? w[c * KD + k0] : 0.f;
        float v1 = (k1 < KD) ? w[c * KD + k1] : 0.f;
        float h0 = bf16_trunc(v0), h1 = bf16_trunc(v1);
        uint2 o;
        o.x = packbf2(h0, h1);
        o.y = packbf2(v0 - h0, v1 - h1);
        g_wbf[l][kp][c] = o;
    }
}

// ---------------- coalesced tiled transpose: [B][C][N] -> [B][N][C], C=64 ----------------
__global__ void __launch_bounds__(256) k_transp(const float* __restrict__ src1,
                                                const float* __restrict__ src2)
{
    __shared__ float t[32][33];
    int zc = blockIdx.y;
    int ct = zc & 1;
    int b = (zc >> 1) & (BATCH - 1);
    int which = zc >> 2;
    const float* src = which ? src2 : src1;
    float* dst = which ? g_p2T : g_p1T;
    int n0 = blockIdx.x * 32;
    int c0 = ct * 32;
    int lx = threadIdx.x & 31, ly = threadIdx.x >> 5;
    #pragma unroll
    for (int r = 0; r < 4; r++) {
        int c = c0 + ly + r * 8;
        t[ly + r * 8][lx] = src[((size_t)b * DD + c) * N1 + n0 + lx];
    }
    __syncthreads();
    #pragma unroll
    for (int r = 0; r < 4; r++) {
        int n = n0 + ly + r * 8;
        dst[((size_t)b * N1 + n) * DD + c0 + lx] = t[lx][ly + r * 8];
    }
}

// ---------------- squared norms of F1/F2 (no rigid dependency) ----------------
__global__ void k_normsAB()
{
    int t = blockIdx.x * blockDim.x + threadIdx.x;
    if (t >= BATCH * 4096) return;
    int b = t / 4096, n = t % 4096;
    float sA = 0.f, sB = 0.f;
    #pragma unroll 8
    for (int c = 0; c < CP; c++) {
        float a = g_F1[(b * CP + c) * 4096 + n];
        float bb = g_F2[(b * CP + c) * 4096 + n];
        sA += a * a;
        sB += bb * bb;
    }
    g_nA[t] = sA;
    g_nB[t] = sB;
}

// ---------------- comb norm (needs rigid + normsAB) ----------------
__global__ void k_nc()
{
    int t = blockIdx.x * blockDim.x + threadIdx.x;
    if (t >= BATCH * N1) return;
    float wf = g_wf[t], wr = g_wr[t];
    float v0 = g_vw[t * 3 + 0], v1 = g_vw[t * 3 + 1], v2 = g_vw[t * 3 + 2];
    g_nC[t] = wf * wf * g_nA[t] + wr * wr * (v0 * v0 + v1 * v1 + v2 * v2);
}

// ---------------- comb features for second KNN ----------------
__global__ void k_comb()
{
    const int total = BATCH * CP * N1;
    for (int e = blockIdx.x * blockDim.x + threadIdx.x; e < total;
         e += gridDim.x * blockDim.x) {
        int b = e / (CP * N1);
        int c = (e / N1) % CP;
        int n = e % N1;
        float v = 0.f;
        if (c < 67) v = g_wf[b * N1 + n] * g_F1[e];
        else if (c < 70) v = g_wr[b * N1 + n] * g_vw[(b * N1 + n) * 3 + (c - 67)];
        g_CB[e] = v;
    }
}

// ---------------- distance GEMM on tensor cores (3xTF32, hi/lo interleaved) ----------------
#define CPK 40
#define S2 132
#define SLAB2 (CPK * S2)
#define DIST_SMEM ((2 * SLAB2 * 2 + 256) * 4)

__global__ void __launch_bounds__(256) k_dist_tc(int sel)
{
    extern __shared__ float2 dsm2[];
    float2* As2 = dsm2;                 // [CPK][S2] (hi,lo)
    float2* Bs2 = As2 + SLAB2;
    float* nAs = (float*)(Bs2 + SLAB2); // 128
    float* nBs = nAs + 128;             // 128

    const float* FA = sel ? g_CB : g_F1;
    const float* FB = sel ? g_CB : g_F2;
    const float* nAv = sel ? g_nC : g_nA;
    const float* nBv = sel ? g_nC : g_nB;

    int b = blockIdx.z;
    int i0 = blockIdx.y * 128, j0 = blockIdx.x * 128;
    const float* Asrc = FA + (size_t)b * CP * N1 + i0;
    const float* Bsrc = FB + (size_t)b * CP * N2 + j0;

    int tid = threadIdx.x;
    if (tid < 128) {
        nAs[tid] = nAv[b * N1 + i0 + tid];
        nBs[tid] = nBv[b * N2 + j0 + tid];
    }

    int warp = tid >> 5, lane = tid & 31;
    int gid = lane >> 2, tig = lane & 3;
    int mi = warp * 16 + gid;

    float acc[16][4];
    #pragma unroll
    for (int nt = 0; nt < 16; nt++)
        #pragma unroll
        for (int u = 0; u < 4; u++) acc[nt][u] = 0.f;

    for (int kb = 0; kb < CP; kb += CPK) {
        for (int idx = tid; idx < CPK * 32 * 2; idx += 256) {
            int which = idx >= CPK * 32;
            int r = which ? idx - CPK * 32 : idx;
            int k = r >> 5, c4 = (r & 31) << 2;
            const float* src = which ? Bsrc : Asrc;
            float2* dst = (which ? Bs2 : As2) + k * S2 + c4;
            float4 v = *(const float4*)(src + (size_t)(kb + k) * 4096 + c4);
            float h;
            h = f2tf32f(v.x); dst[0] = make_float2(h, f2tf32f(v.x - h));
            h = f2tf32f(v.y); dst[1] = make_float2(h, f2tf32f(v.y - h));
            h = f2tf32f(v.z); dst[2] = make_float2(h, f2tf32f(v.z - h));
            h = f2tf32f(v.w); dst[3] = make_float2(h, f2tf32f(v.w - h));
        }
        __syncthreads();

        #pragma unroll
        for (int kk = 0; kk < CPK; kk += 8) {
            const float2* r0 = As2 + (kk + tig) * S2;
            const float2* r1 = As2 + (kk + tig + 4) * S2;
            float2 a0 = r0[mi], a1 = r0[mi + 8];
            float2 a2 = r1[mi], a3 = r1[mi + 8];
            const float2* q0 = Bs2 + (kk + tig) * S2;
            const float2* q1 = Bs2 + (kk + tig + 4) * S2;
            #pragma unroll
            for (int nt = 0; nt < 16; nt++) {
                int nb = nt * 8 + gid;
                float2 b0 = q0[nb], b1 = q1[nb];
                MMA_TF32(acc[nt], a0.y, a1.y, a2.y, a3.y, b0.x, b1.x);  // lo*hi
                MMA_TF32(acc[nt], a0.x, a1.x, a2.x, a3.x, b0.y, b1.y);  // hi*lo
                MMA_TF32(acc[nt], a0.x, a1.x, a2.x, a3.x, b0.x, b1.x);  // hi*hi
            }
        }
        __syncthreads();
    }

    float* drow = g_dist + (size_t)b * N1 * N2;
    float ni0 = nAs[mi], ni1 = nAs[mi + 8];
    size_t ro0 = (size_t)(i0 + mi) * N2 + j0;
    size_t ro1 = ro0 + (size_t)8 * N2;
    #pragma unroll
    for (int nt = 0; nt < 16; nt++) {
        int jc = nt * 8 + tig * 2;
        float nj0 = nBs[jc], nj1 = nBs[jc + 1];
        float2 o0, o1;
        o0.x = fmaxf(ni0 - 2.f * acc[nt][0] + nj0, 0.f);
        o0.y = fmaxf(ni0 - 2.f * acc[nt][1] + nj1, 0.f);
        o1.x = fmaxf(ni1 - 2.f * acc[nt][2] + nj0, 0.f);
        o1.y = fmaxf(ni1 - 2.f * acc[nt][3] + nj1, 0.f);
        *(float2*)(drow + ro0 + jc) = o0;
        *(float2*)(drow + ro1 + jc) = o1;
    }
}

// ---------------- top-K: block build, warp0 register-resident extraction ----------------
__global__ void __launch_bounds__(256) k_topk(int sel)
{
    __shared__ unsigned long long keys[N2];     // 32 KB
    __shared__ unsigned long long segmin[256];
    int q = blockIdx.x;
    const float* row = g_dist + (size_t)q * N2;
    int* idxo = sel ? g_idx2 : g_idx1;
    int tid = threadIdx.x;

    // build: thread tid owns segment tid (16 consecutive values)
    {
        int basej = tid * 16;
        unsigned long long mn = ~0ull;
        #pragma unroll
        for (int i = 0; i < 4; i++) {
            float4 f = *(const float4*)(row + basej + i * 4);
            unsigned long long k0 = ((unsigned long long)__float_as_uint(f.x) << 32) | (unsigned)(basej + i * 4 + 0);
            unsigned long long k1 = ((unsigned long long)__float_as_uint(f.y) << 32) | (unsigned)(basej + i * 4 + 1);
            unsigned long long k2 = ((unsigned long long)__float_as_uint(f.z) << 32) | (unsigned)(basej + i * 4 + 2);
            unsigned long long k3 = ((unsigned long long)__float_as_uint(f.w) << 32) | (unsigned)(basej + i * 4 + 3);
            keys[basej + i * 4 + 0] = k0;
            keys[basej + i * 4 + 1] = k1;
            keys[basej + i * 4 + 2] = k2;
            keys[basej + i * 4 + 3] = k3;
            mn = u64min(mn, u64min(u64min(k0, k1), u64min(k2, k3)));
        }
        segmin[tid] = mn;
    }
    __syncthreads();

    // extraction entirely within warp 0: seg s owned by lane (s & 31), slot (s >> 5)
    if (tid < 32) {
        int lane = tid;
        unsigned long long r[8];
        #pragma unroll
        for (int i = 0; i < 8; i++) r[i] = segmin[lane + 32 * i];

        for (int k = 0; k < KN; k++) {
            unsigned long long m = r[0];
            #pragma unroll
            for (int i = 1; i < 8; i++) m = u64min(m, r[i]);
            #pragma unroll
            for (int o = 16; o; o >>= 1)
                m = u64min(m, __shfl_xor_sync(0xffffffffu, m, o));
            int j = (int)(unsigned)(m & 0xffffffffULL);
            if (lane == 0) {
                idxo[q * KN + k] = j;
                keys[j] = ~0ull;
            }
            if (k == KN - 1) break;
            __syncwarp();
            int seg = j >> 4;
            unsigned long long v = (lane < 16) ? keys[seg * 16 + lane] : ~0ull;
            #pragma unroll
            for (int o = 8; o; o >>= 1)
                v = u64min(v, __shfl_xor_sync(0xffffffffu, v, o));
            unsigned long long vb = __shfl_sync(0xffffffffu, v, 0);
            if (lane == (seg & 31)) r[seg >> 5] = vb;
        }
    }
}

// ---------------- fused MLP on tensor cores (bf16 3-term split, m16n8k16) ----------------
// 512 threads (16 warps), block = 8 points x 16 neighbors = 128 columns.
#define TNP 8
#define SY 132
#define MX   0                        // Xbuf [144][SY] fp32 (rows 131..143 zero)
#define MYO  (144 * SY)               // Ybuf [128][SY] fp32
#define MWC  (MYO + 128 * SY)         // Wc [24 kpairs][SY] uint2
#define MB   (MWC + 24 * SY * 2)      // biases [3][128]
#define MH2  (MB + 384)               // h2s [128][8]
#define MSW2 (MH2 + 1024)             // sw2 [128][8]
#define MSB2 (MSW2 + 1024)            // sb2 [128]
#define MIDX (MSB2 + 128)             // idxs [128]
#define MLP2_SMEM ((MIDX + 128) * 4)

__global__ void __launch_bounds__(512) k_mlp_tc(
    const float* __restrict__ b0g, const float* __restrict__ b1g,
    const float* __restrict__ b2g,
    const float* __restrict__ n1w0, const float* __restrict__ n1b0,
    const float* __restrict__ n1w1, const float* __restrict__ n1b1,
    const float* __restrict__ n1w2, const float* __restrict__ n1b2)
{
    extern __shared__ float sm[];
    float* Xbuf = sm + MX;
    float* Ybuf = sm + MYO;
    uint2* Wc = (uint2*)(sm + MWC);
    float* biasS = sm + MB;
    float* h2s = sm + MH2;
    float* sw2 = sm + MSW2;
    float* sb2 = sm + MSB2;
    int* idxs = (int*)(sm + MIDX);

    int tid = threadIdx.x;
    int warp = tid >> 5, lane = tid & 31;
    int gid = lane >> 2, tig = lane & 3;
    int wm = warp & 7, nh = warp >> 3;
    int mi = wm * 16 + gid;
    int base = blockIdx.x * TNP;

    if (tid < 128) {
        idxs[tid] = g_idx1[base * KN + tid];
        #pragma unroll
        for (int r = 0; r < 8; r++) sw2[tid + 128 * r] = n1w2[tid + 128 * r];
        sb2[tid] = n1b2[tid];
        biasS[tid] = b0g[tid];
        biasS[128 + tid] = b1g[tid];
        biasS[256 + tid] = b2g[tid];
    }
    __syncthreads();

    // stage Xbuf [144][128]
    for (int e = tid; e < 144 * 128; e += 512) {
        int i = e >> 7, col = e & 127;
        int tn = col >> 4;
        int pt = base + tn;
        int b = pt >> 12;
        int j = idxs[col];
        float v;
        if (i < 64) v = g_p1T[(size_t)pt * DD + i];
        else if (i < 128) v = g_p2T[((size_t)b * N2 + j) * DD + (i - 64)];
        else if (i < 131) v = g_x2T[(b * N2 + j) * 3 + (i - 128)] - g_x1T[pt * 3 + (i - 128)];
        else v = 0.f;
        Xbuf[i * SY + col] = v;
    }
    __syncthreads();

    // weight-net 1 (3->8->8) per column -> h2s[col][8]
    if (tid < 128) {
        int col = tid;
        float dx0 = Xbuf[128 * SY + col];
        float dx1 = Xbuf[129 * SY + col];
        float dx2 = Xbuf[130 * SY + col];
        float h[8];
        #pragma unroll
        for (int j = 0; j < 8; j++) {
            float s = n1w0[j * 3 + 0] * dx0 + n1w0[j * 3 + 1] * dx1 + n1w0[j * 3 + 2] * dx2 + n1b0[j];
            h[j] = fmaxf(s, 0.f);
        }
        #pragma unroll
        for (int j = 0; j < 8; j++) {
            float s = n1b1[j];
            #pragma unroll
            for (int m = 0; m < 8; m++) s += n1w1[j * 8 + m] * h[m];
            h2s[col * 8 + j] = fmaxf(s, 0.f);
        }
    }

    // ---- three GEMM layers (bf16 3-term) ----
    #pragma unroll 1
    for (int l = 0; l < 3; l++) {
        const int KPL = (l == 0) ? 72 : 64;   // k-pairs
        const float* Xin = (l == 1) ? Ybuf : Xbuf;
        float* Yout = (l == 1) ? Xbuf : Ybuf;

        float acc[8][4];
        #pragma unroll
        for (int nti = 0; nti < 8; nti++) {
            int c0 = (nh * 8 + nti) * 8 + tig * 2;
            acc[nti][0] = biasS[l * 128 + c0];
            acc[nti][1] = biasS[l * 128 + c0 + 1];
            acc[nti][2] = acc[nti][0];
            acc[nti][3] = acc[nti][1];
        }

        for (int kbp = 0; kbp < KPL; kbp += 24) {
            int cs = (KPL - kbp < 24) ? (KPL - kbp) : 24;
            __syncthreads();
            for (int e = tid; e < cs * 128; e += 512) {
                int kl = e >> 7, c = e & 127;
                Wc[kl * SY + c] = g_wbf[l][kbp + kl][c];
            }
            __syncthreads();
            for (int pp = 0; pp < cs; pp += 8) {
                int kp0 = kbp + pp + tig;       // kpair for a0/a1 (k = 2kp0, 2kp0+1)
                int kp1 = kp0 + 4;              // kpair for a2/a3
                int r00 = 2 * kp0, r10 = 2 * kp1;
                float x00 = Xin[r00 * SY + mi];
                float x01 = Xin[(r00 + 1) * SY + mi];
                float x02 = Xin[r00 * SY + mi + 8];
                float x03 = Xin[(r00 + 1) * SY + mi + 8];
                float x10 = Xin[r10 * SY + mi];
                float x11 = Xin[(r10 + 1) * SY + mi];
                float x12 = Xin[r10 * SY + mi + 8];
                float x13 = Xin[(r10 + 1) * SY + mi + 8];
                float h00 = bf16_trunc(x00), h01 = bf16_trunc(x01);
                float h02 = bf16_trunc(x02), h03 = bf16_trunc(x03);
                float h10 = bf16_trunc(x10), h11 = bf16_trunc(x11);
                float h12 = bf16_trunc(x12), h13 = bf16_trunc(x13);
                unsigned a0h = packbf2(h00, h01), a1h = packbf2(h02, h03);
                unsigned a2h = packbf2(h10, h11), a3h = packbf2(h12, h13);
                unsigned a0l = packbf2(x00 - h00, x01 - h01);
                unsigned a1l = packbf2(x02 - h02, x03 - h03);
                unsigned a2l = packbf2(x10 - h10, x11 - h11);
                unsigned a3l = packbf2(x12 - h12, x13 - h13);
                const uint2* w0p = Wc + (pp + tig) * SY;
                const uint2* w1p = Wc + (pp + tig + 4) * SY;
                #pragma unroll
                for (int nti = 0; nti < 8; nti++) {
                    int nb = (nh * 8 + nti) * 8 + gid;
                    uint2 b0 = w0p[nb], b1 = w1p[nb];
                    MMA_BF16(acc[nti], a0l, a1l, a2l, a3l, b0.x, b1.x);  // lo*hi
                    MMA_BF16(acc[nti], a0h, a1h, a2h, a3h, b0.y, b1.y);  // hi*lo
                    MMA_BF16(acc[nti], a0h, a1h, a2h, a3h, b0.x, b1.x);  // hi*hi
                }
            }
        }
        __syncthreads();
        #pragma unroll
        for (int nti = 0; nti < 8; nti++) {
            int c0 = (nh * 8 + nti) * 8 + tig * 2;
            Yout[c0 * SY + mi] = leakyf(acc[nti][0]);
            Yout[(c0 + 1) * SY + mi] = leakyf(acc[nti][1]);
            Yout[c0 * SY + mi + 8] = leakyf(acc[nti][2]);
            Yout[(c0 + 1) * SY + mi + 8] = leakyf(acc[nti][3]);
        }
    }
    __syncthreads();
    // Y3 (leaky applied) is in Ybuf[c][col].

    // ---- S matrix into Xbuf[col][c] ----
    {
        int col = tid >> 2, cq = tid & 3;
        float hj[8];
        #pragma unroll
        for (int j = 0; j < 8; j++) hj[j] = h2s[col * 8 + j];
        #pragma unroll 4
        for (int cc = 0; cc < 32; cc++) {
            int c = cq * 32 + cc;
            float s = sb2[c];
            #pragma unroll
            for (int j = 0; j < 8; j++) s += sw2[c * 8 + j] * hj[j];
            Xbuf[col * SY + c] = fmaxf(s, 0.f);
        }
    }
    __syncthreads();

    // ---- p2p[pt][c] = sum_k S[pt*16+k][c] * Y3[c][pt*16+k] ----
    for (int e = tid; e < 1024; e += 512) {
        int pt = e >> 7, c = e & 127;
        const float* yr = Ybuf + c * SY + pt * 16;
        const float* sc = Xbuf + (pt * 16) * SY + c;
        float a = 0.f;
        #pragma unroll
        for (int k = 0; k < 16; k++) a += sc[k * SY] * yr[k];
        g_p2p[(size_t)(base + pt) * CO + c] = a;
    }
}

// ---------------- patch aggregation ----------------
__global__ void __launch_bounds__(128) k_patch(
    const float* __restrict__ n2w0, const float* __restrict__ n2b0,
    const float* __restrict__ n2w1, const float* __restrict__ n2b1,
    const float* __restrict__ n2w2, const float* __restrict__ n2b2,
    float* __restrict__ out)
{
    __shared__ float h2s[16][8];
    __shared__ int js[16];
    int q = blockIdx.x;
    int b = q / N1, n = q % N1;
    int tid = threadIdx.x;
    if (tid < 16) {
        int j = g_idx2[q * KN + tid];
        js[tid] = j;
        float dx0 = g_x1T[(b * N1 + j) * 3 + 0] - g_x1T[q * 3 + 0];
        float dx1 = g_x1T[(b * N1 + j) * 3 + 1] - g_x1T[q * 3 + 1];
        float dx2 = g_x1T[(b * N1 + j) * 3 + 2] - g_x1T[q * 3 + 2];
        float h[8];
        #pragma unroll
        for (int jj = 0; jj < 8; jj++) {
            float s = n2w0[jj * 3 + 0] * dx0 + n2w0[jj * 3 + 1] * dx1 + n2w0[jj * 3 + 2] * dx2 + n2b0[jj];
            h[jj] = fmaxf(s, 0.f);
        }
        #pragma unroll
        for (int jj = 0; jj < 8; jj++) {
            float s = n2b1[jj];
            #pragma unroll
            for (int m = 0; m < 8; m++) s += n2w1[jj * 8 + m] * h[m];
            h2s[tid][jj] = fmaxf(s, 0.f);
        }
    }
    __syncthreads();
    int c = tid;
    float w2r[8];
    #pragma unroll
    for (int j = 0; j < 8; j++) w2r[j] = n2w2[c * 8 + j];
    float bc = n2b2[c];
    float acc = 0.f;
    #pragma unroll
    for (int k = 0; k < KN; k++) {
        float s = bc;
        #pragma unroll
        for (int j = 0; j < 8; j++) s += w2r[j] * h2s[k][j];
        s = fmaxf(s, 0.f);
        acc += s * g_p2p[((size_t)b * N1 + js[k]) * CO + c];
    }
    out[(size_t)b * CO * N1 + (size_t)c * N1 + n] = acc;
}

// ---------------- launch ----------------
extern "C" void kernel_launch(void* const* d_in, const int* in_sizes, int n_in,
                              void* d_out, int out_size)
{
    int s = (n_in >= 31) ? 0 : -2;
    const float* xyz1 = (const float*)d_in[0];
    const float* xyz2 = (const float*)d_in[1];
    const float* pts1 = (const float*)d_in[2];
    const float* pts2 = (const float*)d_in[3];
    const float* vel1 = (const float*)d_in[4];
    const float* fcc  = (const float*)d_in[8 + s];
    const float* fcv  = (const float*)d_in[9 + s];
    const float* wxyz = (const float*)d_in[10 + s];
    const float* wpts = (const float*)d_in[12 + s];
    const float* mw0 = (const float*)d_in[13 + s];
    const float* mb0 = (const float*)d_in[14 + s];
    const float* mw1 = (const float*)d_in[15 + s];
    const float* mb1 = (const float*)d_in[16 + s];
    const float* mw2 = (const float*)d_in[17 + s];
    const float* mb2 = (const float*)d_in[18 + s];
    const float* n1w0 = (const float*)d_in[19 + s];
    const float* n1b0 = (const float*)d_in[20 + s];
    const float* n2w0 = (const float*)d_in[21 + s];
    const float* n2b0 = (const float*)d_in[22 + s];
    const float* n1w1 = (const float*)d_in[23 + s];
    const float* n1b1 = (const float*)d_in[24 + s];
    const float* n2w1 = (const float*)d_in[25 + s];
    const float* n2b1 = (const float*)d_in[26 + s];
    const float* n1w2 = (const float*)d_in[27 + s];
    const float* n1b2 = (const float*)d_in[28 + s];
    const float* n2w2 = (const float*)d_in[29 + s];
    const float* n2b2 = (const float*)d_in[30 + s];

    float* out = (float*)d_out;
    const int patch_elems = BATCH * CO * N1;
    const int vw_elems = BATCH * N1 * 3;
    float* out_vw = (out_size >= patch_elems + vw_elems) ? (out + patch_elems) : nullptr;

    cudaFuncSetAttribute(k_mlp_tc, cudaFuncAttributeMaxDynamicSharedMemorySize, (int)MLP2_SMEM);
    cudaFuncSetAttribute(k_dist_tc, cudaFuncAttributeMaxDynamicSharedMemorySize, (int)DIST_SMEM);

    const int prep_total = 2 * BATCH * CP * N1 + 2 * BATCH * 3 * N1;
    dim3 gg(N2 / 128, N1 / 128, BATCH);
    dim3 gt(N1 / 32, 2 * BATCH * 2);

    // order: topk0 is the 4th launch -> ncu lands on the new top-k
    k_prep<<<(prep_total + 255) / 256, 256>>>(xyz1, xyz2, pts1, pts2, wxyz, wpts);
    k_normsAB<<<(BATCH * 4096 + 127) / 128, 128>>>();
    k_dist_tc<<<gg, 256, DIST_SMEM>>>(0);
    k_topk<<<BATCH * N1, 256>>>(0);
    k_rigid<<<(BATCH * N1 + 127) / 128, 128>>>(xyz1, vel1, fcc, fcv, out_vw);
    k_nc<<<(BATCH * N1 + 127) / 128, 128>>>();
    k_transp<<<gt, 256>>>(pts1, pts2);
    k_wprep<<<108, 256>>>(mw0, mw1, mw2);
    k_mlp_tc<<<(BATCH * N1) / TNP, 512, MLP2_SMEM>>>(mb0, mb1, mb2,
                                                     n1w0, n1b0, n1w1, n1b1, n1w2, n1b2);
    k_comb<<<(BATCH * CP * N1 + 255) / 256, 256>>>();
    k_dist_tc<<<gg, 256, DIST_SMEM>>>(1);
    k_topk<<<BATCH * N1, 256>>>(1);
    k_patch<<<BATCH * N1, 128>>>(n2w0, n2b0, n2w1, n2b1, n2w2, n2b2, out);
}

// round 10
// speedup vs baseline: 1.5352x; 1.1322x over previous
#include <cuda_runtime.h>
#include <cuda_bf16.h>
#include <math.h>

#define BATCH 2
#define N1 4096
#define N2 4096
#define DD 64
#define KN 16
#define KCC 8
#define CP 80      // padded feature channels (67 / 70 used)
#define CO 128

// ---------------- scratch (static device memory; no runtime alloc) ----------------
__device__ float g_dist[(size_t)BATCH * N1 * N2];        // 134 MB
__device__ float g_F1[BATCH * CP * N1];
__device__ float g_F2[BATCH * CP * N2];
__device__ float g_CB[BATCH * CP * N1];
__device__ float g_nA[BATCH * N1];
__device__ float g_nB[BATCH * N2];
__device__ float g_nC[BATCH * N1];
__device__ int   g_idx1[BATCH * N1 * KN];
__device__ int   g_idx2[BATCH * N1 * KN];
__device__ float g_vw[BATCH * N1 * 3];
__device__ float g_wf[BATCH * N1];
__device__ float g_wr[BATCH * N1];
__device__ float g_p1T[BATCH * N1 * DD];
__device__ float g_p2T[BATCH * N2 * DD];
__device__ float g_x1T[BATCH * N1 * 3];
__device__ float g_x2T[BATCH * N2 * 3];
__device__ float g_p2p[(size_t)BATCH * N1 * CO];
__device__ uint2 g_wbf[3][72][128];     // bf16 hi/lo split, transposed MLP weights (k-pairs)

__device__ __forceinline__ float leakyf(float x) { return x >= 0.f ? x : 0.1f * x; }
__device__ __forceinline__ unsigned long long u64min(unsigned long long a, unsigned long long b) {
    return a < b ? a : b;
}

// ---- tf32 helpers (dist kernel) ----
__device__ __forceinline__ float f2tf32f(float x) {
    unsigned int r;
    asm("cvt.rna.tf32.f32 %0, %1;" : "=r"(r) : "f"(x));
    return __uint_as_float(r);
}

#define MMA_TF32(acc, A0, A1, A2, A3, B0, B1)                                   \
    asm volatile("mma.sync.aligned.m16n8k8.row.col.f32.tf32.tf32.f32 "          \
                 "{%0,%1,%2,%3}, {%4,%5,%6,%7}, {%8,%9}, {%0,%1,%2,%3};"        \
                 : "+f"(acc[0]), "+f"(acc[1]), "+f"(acc[2]), "+f"(acc[3])       \
                 : "r"(__float_as_uint(A0)), "r"(__float_as_uint(A1)),          \
                   "r"(__float_as_uint(A2)), "r"(__float_as_uint(A3)),          \
                   "r"(__float_as_uint(B0)), "r"(__float_as_uint(B1)))

// ---- bf16 helpers (mlp kernel) ----
__device__ __forceinline__ float bf16_trunc(float x) {          // exact split: top 16 bits
    return __uint_as_float(__float_as_uint(x) & 0xffff0000u);
}
__device__ __forceinline__ unsigned packbf2(float lo_elem, float hi_elem) {
    __nv_bfloat162 v = __floats2bfloat162_rn(lo_elem, hi_elem); // .x = first arg (low half)
    return *(unsigned*)&v;
}

#define MMA_BF16(acc, A0, A1, A2, A3, B0, B1)                                   \
    asm volatile("mma.sync.aligned.m16n8k16.row.col.f32.bf16.bf16.f32 "         \
                 "{%0,%1,%2,%3}, {%4,%5,%6,%7}, {%8,%9}, {%0,%1,%2,%3};"        \
                 : "+f"(acc[0]), "+f"(acc[1]), "+f"(acc[2]), "+f"(acc[3])       \
                 : "r"(A0), "r"(A1), "r"(A2), "r"(A3), "r"(B0), "r"(B1))

// ---------------- rigid 3x3 least squares + mask ----------------
__global__ void k_rigid(const float* __restrict__ xyz1, const float* __restrict__ vel1,
                        const float* __restrict__ fcc, const float* __restrict__ fcv,
                        float* __restrict__ out_vw)
{
    int t = blockIdx.x * blockDim.x + threadIdx.x;
    if (t >= BATCH * N1) return;
    int b = t / N1, n = t % N1;
    const float* cc = fcc + (size_t)t * KCC * 3;
    const float* cv = fcv + (size_t)t * KCC;
    double A00 = 1e-6, A01 = 0, A02 = 0, A11 = 1e-6, A12 = 0, A22 = 1e-6;
    double r0 = 0, r1 = 0, r2 = 0;
    for (int k = 0; k < KCC; k++) {
        double x = cc[k * 3 + 0], y = cc[k * 3 + 1], z = cc[k * 3 + 2];
        double inv = 1.0 / sqrt(x * x + y * y + z * z);
        x *= inv; y *= inv; z *= inv;
        A00 += x * x; A01 += x * y; A02 += x * z;
        A11 += y * y; A12 += y * z; A22 += z * z;
        double v = (double)cv[k];
        r0 += x * v; r1 += y * v; r2 += z * v;
    }
    double c00 = A11 * A22 - A12 * A12;
    double c01 = A01 * A22 - A12 * A02;
    double c02 = A01 * A12 - A11 * A02;
    double det = A00 * c00 - A01 * c01 + A02 * c02;
    double id = 1.0 / det;
    double v0 = (r0 * c00 - A01 * (r1 * A22 - A12 * r2) + A02 * (r1 * A12 - A11 * r2)) * id;
    double v1 = (A00 * (r1 * A22 - A12 * r2) - r0 * c01 + A02 * (A01 * r2 - r1 * A02)) * id;
    double v2 = (A00 * (A11 * r2 - r1 * A12) - A01 * (A01 * r2 - r1 * A02) + r0 * c02) * id;

    float fx = xyz1[(b * 3 + 0) * N1 + n];
    float fy = xyz1[(b * 3 + 1) * N1 + n];
    float fz = xyz1[(b * 3 + 2) * N1 + n];
    double inl = 1.0 / sqrt((double)fx * fx + (double)fy * fy + (double)fz * fz);
    double err = fabs((v0 * fx + v1 * fy + v2 * fz) * inl - (double)vel1[t]);
    bool m = (err <= 5.0);
    g_wf[t] = m ? 0.1f : 0.9f;
    g_wr[t] = m ? 0.9f : 0.1f;
    g_vw[t * 3 + 0] = (float)v0;
    g_vw[t * 3 + 1] = (float)v1;
    g_vw[t * 3 + 2] = (float)v2;
    if (out_vw) {
        out_vw[t * 3 + 0] = (float)v0;
        out_vw[t * 3 + 1] = (float)v1;
        out_vw[t * 3 + 2] = (float)v2;
    }
}

// ---------------- fused: weighted feature build + xyz transposes ----------------
__global__ void k_prep(const float* __restrict__ xyz1, const float* __restrict__ xyz2,
                       const float* __restrict__ pts1, const float* __restrict__ pts2,
                       const float* __restrict__ wxyz_p, const float* __restrict__ wpts_p)
{
    float wx = *wxyz_p, wp = *wpts_p;
    const int totalF = BATCH * CP * N1;
    const int tx3 = BATCH * 3 * N1;
    const int total = 2 * totalF + 2 * tx3;
    for (int e = blockIdx.x * blockDim.x + threadIdx.x; e < total;
         e += gridDim.x * blockDim.x) {
        if (e < 2 * totalF) {
            int which = e / totalF;
            int r = e % totalF;
            int b = r / (CP * N1);
            int c = (r / N1) % CP;
            int n = r % N1;
            const float* xyz = which ? xyz2 : xyz1;
            const float* pts = which ? pts2 : pts1;
            float* F = which ? g_F2 : g_F1;
            float v = 0.f;
            if (c < 3) v = wx * xyz[(b * 3 + c) * N1 + n];
            else if (c < 67) v = wp * pts[(b * DD + (c - 3)) * N1 + n];
            F[r] = v;
        } else {
            int r = e - 2 * totalF;
            if (r < tx3) {
                int b = r / (3 * N1), c = (r / N1) % 3, n = r % N1;
                g_x1T[(b * N1 + n) * 3 + c] = xyz1[r];
            } else {
                r -= tx3;
                int b = r / (3 * N1), c = (r / N1) % 3, n = r % N1;
                g_x2T[(b * N2 + n) * 3 + c] = xyz2[r];
            }
        }
    }
}

// ---------------- MLP weight transpose + bf16 hi/lo split (runs once) ----------------
__global__ void k_wprep(const float* __restrict__ w0, const float* __restrict__ w1,
                        const float* __restrict__ w2)
{
    const int per = 72 * 128;
    for (int e = blockIdx.x * blockDim.x + threadIdx.x; e < 3 * per;
         e += gridDim.x * blockDim.x) {
        int l = e / per;
        int r = e % per;
        int kp = r >> 7, c = r & 127;
        int KD = (l == 0) ? 131 : 128;
        const float* w = (l == 0) ? w0 : (l == 1) ? w1 : w2;
        int k0 = 2 * kp, k1 = 2 * kp + 1;
        float v0 = (k0 < KD) ? w[c * KD + k0] : 0.f;
        float v1 = (k1 < KD) ? w[c * KD + k1] : 0.f;
        float h0 = bf16_trunc(v0), h1 = bf16_trunc(v1);
        uint2 o;
        o.x = packbf2(h0, h1);
        o.y = packbf2(v0 - h0, v1 - h1);
        g_wbf[l][kp][c] = o;
    }
}

// ---------------- coalesced tiled transpose: [B][C][N] -> [B][N][C], C=64 ----------------
__global__ void __launch_bounds__(256) k_transp(const float* __restrict__ src1,
                                                const float* __restrict__ src2)
{
    __shared__ float t[32][33];
    int zc = blockIdx.y;
    int ct = zc & 1;
    int b = (zc >> 1) & (BATCH - 1);
    int which = zc >> 2;
    const float* src = which ? src2 : src1;
    float* dst = which ? g_p2T : g_p1T;
    int n0 = blockIdx.x * 32;
    int c0 = ct * 32;
    int lx = threadIdx.x & 31, ly = threadIdx.x >> 5;
    #pragma unroll
    for (int r = 0; r < 4; r++) {
        int c = c0 + ly + r * 8;
        t[ly + r * 8][lx] = src[((size_t)b * DD + c) * N1 + n0 + lx];
    }
    __syncthreads();
    #pragma unroll
    for (int r = 0; r < 4; r++) {
        int n = n0 + ly + r * 8;
        dst[((size_t)b * N1 + n) * DD + c0 + lx] = t[lx][ly + r * 8];
    }
}

// ---------------- squared norms of F1/F2 (no rigid dependency) ----------------
__global__ void k_normsAB()
{
    int t = blockIdx.x * blockDim.x + threadIdx.x;
    if (t >= BATCH * 4096) return;
    int b = t / 4096, n = t % 4096;
    float sA = 0.f, sB = 0.f;
    #pragma unroll 8
    for (int c = 0; c < CP; c++) {
        float a = g_F1[(b * CP + c) * 4096 + n];
        float bb = g_F2[(b * CP + c) * 4096 + n];
        sA += a * a;
        sB += bb * bb;
    }
    g_nA[t] = sA;
    g_nB[t] = sB;
}

// ---------------- comb norm (needs rigid + normsAB) ----------------
__global__ void k_nc()
{
    int t = blockIdx.x * blockDim.x + threadIdx.x;
    if (t >= BATCH * N1) return;
    float wf = g_wf[t], wr = g_wr[t];
    float v0 = g_vw[t * 3 + 0], v1 = g_vw[t * 3 + 1], v2 = g_vw[t * 3 + 2];
    g_nC[t] = wf * wf * g_nA[t] + wr * wr * (v0 * v0 + v1 * v1 + v2 * v2);
}

// ---------------- comb features for second KNN ----------------
__global__ void k_comb()
{
    const int total = BATCH * CP * N1;
    for (int e = blockIdx.x * blockDim.x + threadIdx.x; e < total;
         e += gridDim.x * blockDim.x) {
        int b = e / (CP * N1);
        int c = (e / N1) % CP;
        int n = e % N1;
        float v = 0.f;
        if (c < 67) v = g_wf[b * N1 + n] * g_F1[e];
        else if (c < 70) v = g_wr[b * N1 + n] * g_vw[(b * N1 + n) * 3 + (c - 67)];
        g_CB[e] = v;
    }
}

// ---------------- distance GEMM on tensor cores (3xTF32, hi/lo interleaved) ----------------
// CPK=16 -> smem 34.8 KB -> 6 CTAs/SM (48 warps) for LDS-latency hiding.
#define CPK 16
#define S2 132
#define SLAB2 (CPK * S2)
#define DIST_SMEM ((2 * SLAB2 * 2 + 256) * 4)

__global__ void __launch_bounds__(256) k_dist_tc(int sel)
{
    extern __shared__ float2 dsm2[];
    float2* As2 = dsm2;                 // [CPK][S2] (hi,lo)
    float2* Bs2 = As2 + SLAB2;
    float* nAs = (float*)(Bs2 + SLAB2); // 128
    float* nBs = nAs + 128;             // 128

    const float* FA = sel ? g_CB : g_F1;
    const float* FB = sel ? g_CB : g_F2;
    const float* nAv = sel ? g_nC : g_nA;
    const float* nBv = sel ? g_nC : g_nB;

    int b = blockIdx.z;
    int i0 = blockIdx.y * 128, j0 = blockIdx.x * 128;
    const float* Asrc = FA + (size_t)b * CP * N1 + i0;
    const float* Bsrc = FB + (size_t)b * CP * N2 + j0;

    int tid = threadIdx.x;
    if (tid < 128) {
        nAs[tid] = nAv[b * N1 + i0 + tid];
        nBs[tid] = nBv[b * N2 + j0 + tid];
    }

    int warp = tid >> 5, lane = tid & 31;
    int gid = lane >> 2, tig = lane & 3;
    int mi = warp * 16 + gid;

    float acc[16][4];
    #pragma unroll
    for (int nt = 0; nt < 16; nt++)
        #pragma unroll
        for (int u = 0; u < 4; u++) acc[nt][u] = 0.f;

    for (int kb = 0; kb < CP; kb += CPK) {
        for (int idx = tid; idx < CPK * 32 * 2; idx += 256) {
            int which = idx >= CPK * 32;
            int r = which ? idx - CPK * 32 : idx;
            int k = r >> 5, c4 = (r & 31) << 2;
            const float* src = which ? Bsrc : Asrc;
            float2* dst = (which ? Bs2 : As2) + k * S2 + c4;
            float4 v = *(const float4*)(src + (size_t)(kb + k) * 4096 + c4);
            float h;
            h = f2tf32f(v.x); dst[0] = make_float2(h, f2tf32f(v.x - h));
            h = f2tf32f(v.y); dst[1] = make_float2(h, f2tf32f(v.y - h));
            h = f2tf32f(v.z); dst[2] = make_float2(h, f2tf32f(v.z - h));
            h = f2tf32f(v.w); dst[3] = make_float2(h, f2tf32f(v.w - h));
        }
        __syncthreads();

        #pragma unroll
        for (int kk = 0; kk < CPK; kk += 8) {
            const float2* r0 = As2 + (kk + tig) * S2;
            const float2* r1 = As2 + (kk + tig + 4) * S2;
            float2 a0 = r0[mi], a1 = r0[mi + 8];
            float2 a2 = r1[mi], a3 = r1[mi + 8];
            const float2* q0 = Bs2 + (kk + tig) * S2;
            const float2* q1 = Bs2 + (kk + tig + 4) * S2;
            #pragma unroll
            for (int nt = 0; nt < 16; nt++) {
                int nb = nt * 8 + gid;
                float2 b0 = q0[nb], b1 = q1[nb];
                MMA_TF32(acc[nt], a0.y, a1.y, a2.y, a3.y, b0.x, b1.x);  // lo*hi
                MMA_TF32(acc[nt], a0.x, a1.x, a2.x, a3.x, b0.y, b1.y);  // hi*lo
                MMA_TF32(acc[nt], a0.x, a1.x, a2.x, a3.x, b0.x, b1.x);  // hi*hi
            }
        }
        __syncthreads();
    }

    float* drow = g_dist + (size_t)b * N1 * N2;
    float ni0 = nAs[mi], ni1 = nAs[mi + 8];
    size_t ro0 = (size_t)(i0 + mi) * N2 + j0;
    size_t ro1 = ro0 + (size_t)8 * N2;
    #pragma unroll
    for (int nt = 0; nt < 16; nt++) {
        int jc = nt * 8 + tig * 2;
        float nj0 = nBs[jc], nj1 = nBs[jc + 1];
        float2 o0, o1;
        o0.x = fmaxf(ni0 - 2.f * acc[nt][0] + nj0, 0.f);
        o0.y = fmaxf(ni0 - 2.f * acc[nt][1] + nj1, 0.f);
        o1.x = fmaxf(ni1 - 2.f * acc[nt][2] + nj0, 0.f);
        o1.y = fmaxf(ni1 - 2.f * acc[nt][3] + nj1, 0.f);
        *(float2*)(drow + ro0 + jc) = o0;
        *(float2*)(drow + ro1 + jc) = o1;
    }
}

// ---------------- top-K: lean build (no keys smem) + warp0 extraction w/ gmem rescan ----------------
__global__ void __launch_bounds__(256) k_topk(int sel)
{
    __shared__ unsigned long long segmin[256];   // 2 KB total smem
    int q = blockIdx.x;
    const float* row = g_dist + (size_t)q * N2;
    int* idxo = sel ? g_idx2 : g_idx1;
    int tid = threadIdx.x;

    // build: thread tid computes min key of its 16 contiguous values (registers only)
    {
        int basej = tid * 16;
        unsigned long long mn = ~0ull;
        #pragma unroll
        for (int i = 0; i < 4; i++) {
            float4 f = *(const float4*)(row + basej + i * 4);
            unsigned long long k0 = ((unsigned long long)__float_as_uint(f.x) << 32) | (unsigned)(basej + i * 4 + 0);
            unsigned long long k1 = ((unsigned long long)__float_as_uint(f.y) << 32) | (unsigned)(basej + i * 4 + 1);
            unsigned long long k2 = ((unsigned long long)__float_as_uint(f.z) << 32) | (unsigned)(basej + i * 4 + 2);
            unsigned long long k3 = ((unsigned long long)__float_as_uint(f.w) << 32) | (unsigned)(basej + i * 4 + 3);
            mn = u64min(mn, u64min(u64min(k0, k1), u64min(k2, k3)));
        }
        segmin[tid] = mn;
    }
    __syncthreads();

    // extraction in warp 0; seg s lives in r[s>>5] of lane (s&31)
    if (tid < 32) {
        int lane = tid;
        unsigned long long r[8];
        #pragma unroll
        for (int i = 0; i < 8; i++) r[i] = segmin[lane + 32 * i];
        int ex[KN];
        #pragma unroll
        for (int i = 0; i < KN; i++) ex[i] = -1;

        for (int k = 0; k < KN; k++) {
            unsigned long long m = r[0];
            #pragma unroll
            for (int i = 1; i < 8; i++) m = u64min(m, r[i]);
            #pragma unroll
            for (int o = 16; o; o >>= 1)
                m = u64min(m, __shfl_xor_sync(0xffffffffu, m, o));
            int j = (int)(unsigned)(m & 0xffffffffULL);
            #pragma unroll
            for (int i = 0; i < KN; i++) if (i == k) ex[i] = j;
            if (lane == 0) idxo[q * KN + k] = j;
            if (k == KN - 1) break;

            // rescan winning segment from gmem, masking extracted indices
            int seg = j >> 4;
            unsigned long long v = ~0ull;
            if (lane < 16) {
                int idx = seg * 16 + lane;
                float f = __ldg(row + idx);
                v = ((unsigned long long)__float_as_uint(f) << 32) | (unsigned)idx;
                #pragma unroll
                for (int i = 0; i < KN; i++)
                    if (i <= k && ex[i] == idx) v = ~0ull;
            }
            #pragma unroll
            for (int o = 8; o; o >>= 1)
                v = u64min(v, __shfl_xor_sync(0xffffffffu, v, o));
            unsigned long long vb = __shfl_sync(0xffffffffu, v, 0);
            int slot = seg >> 5, ln = seg & 31;
            #pragma unroll
            for (int i = 0; i < 8; i++)
                if (i == slot && lane == ln) r[i] = vb;
        }
    }
}

// ---------------- fused MLP on tensor cores (bf16 3-term split, m16n8k16) ----------------
#define TNP 8
#define SY 132
#define MX   0
#define MYO  (144 * SY)
#define MWC  (MYO + 128 * SY)
#define MB   (MWC + 24 * SY * 2)
#define MH2  (MB + 384)
#define MSW2 (MH2 + 1024)
#define MSB2 (MSW2 + 1024)
#define MIDX (MSB2 + 128)
#define MLP2_SMEM ((MIDX + 128) * 4)

__global__ void __launch_bounds__(512) k_mlp_tc(
    const float* __restrict__ b0g, const float* __restrict__ b1g,
    const float* __restrict__ b2g,
    const float* __restrict__ n1w0, const float* __restrict__ n1b0,
    const float* __restrict__ n1w1, const float* __restrict__ n1b1,
    const float* __restrict__ n1w2, const float* __restrict__ n1b2)
{
    extern __shared__ float sm[];
    float* Xbuf = sm + MX;
    float* Ybuf = sm + MYO;
    uint2* Wc = (uint2*)(sm + MWC);
    float* biasS = sm + MB;
    float* h2s = sm + MH2;
    float* sw2 = sm + MSW2;
    float* sb2 = sm + MSB2;
    int* idxs = (int*)(sm + MIDX);

    int tid = threadIdx.x;
    int warp = tid >> 5, lane = tid & 31;
    int gid = lane >> 2, tig = lane & 3;
    int wm = warp & 7, nh = warp >> 3;
    int mi = wm * 16 + gid;
    int base = blockIdx.x * TNP;

    if (tid < 128) {
        idxs[tid] = g_idx1[base * KN + tid];
        #pragma unroll
        for (int r = 0; r < 8; r++) sw2[tid + 128 * r] = n1w2[tid + 128 * r];
        sb2[tid] = n1b2[tid];
        biasS[tid] = b0g[tid];
        biasS[128 + tid] = b1g[tid];
        biasS[256 + tid] = b2g[tid];
    }
    __syncthreads();

    for (int e = tid; e < 144 * 128; e += 512) {
        int i = e >> 7, col = e & 127;
        int tn = col >> 4;
        int pt = base + tn;
        int b = pt >> 12;
        int j = idxs[col];
        float v;
        if (i < 64) v = g_p1T[(size_t)pt * DD + i];
        else if (i < 128) v = g_p2T[((size_t)b * N2 + j) * DD + (i - 64)];
        else if (i < 131) v = g_x2T[(b * N2 + j) * 3 + (i - 128)] - g_x1T[pt * 3 + (i - 128)];
        else v = 0.f;
        Xbuf[i * SY + col] = v;
    }
    __syncthreads();

    if (tid < 128) {
        int col = tid;
        float dx0 = Xbuf[128 * SY + col];
        float dx1 = Xbuf[129 * SY + col];
        float dx2 = Xbuf[130 * SY + col];
        float h[8];
        #pragma unroll
        for (int j = 0; j < 8; j++) {
            float s = n1w0[j * 3 + 0] * dx0 + n1w0[j * 3 + 1] * dx1 + n1w0[j * 3 + 2] * dx2 + n1b0[j];
            h[j] = fmaxf(s, 0.f);
        }
        #pragma unroll
        for (int j = 0; j < 8; j++) {
            float s = n1b1[j];
            #pragma unroll
            for (int m = 0; m < 8; m++) s += n1w1[j * 8 + m] * h[m];
            h2s[col * 8 + j] = fmaxf(s, 0.f);
        }
    }

    #pragma unroll 1
    for (int l = 0; l < 3; l++) {
        const int KPL = (l == 0) ? 72 : 64;
        const float* Xin = (l == 1) ? Ybuf : Xbuf;
        float* Yout = (l == 1) ? Xbuf : Ybuf;

        float acc[8][4];
        #pragma unroll
        for (int nti = 0; nti < 8; nti++) {
            int c0 = (nh * 8 + nti) * 8 + tig * 2;
            acc[nti][0] = biasS[l * 128 + c0];
            acc[nti][1] = biasS[l * 128 + c0 + 1];
            acc[nti][2] = acc[nti][0];
            acc[nti][3] = acc[nti][1];
        }

        for (int kbp = 0; kbp < KPL; kbp += 24) {
            int cs = (KPL - kbp < 24) ? (KPL - kbp) : 24;
            __syncthreads();
            for (int e = tid; e < cs * 128; e += 512) {
                int kl = e >> 7, c = e & 127;
                Wc[kl * SY + c] = g_wbf[l][kbp + kl][c];
            }
            __syncthreads();
            for (int pp = 0; pp < cs; pp += 8) {
                int kp0 = kbp + pp + tig;
                int kp1 = kp0 + 4;
                int r00 = 2 * kp0, r10 = 2 * kp1;
                float x00 = Xin[r00 * SY + mi];
                float x01 = Xin[(r00 + 1) * SY + mi];
                float x02 = Xin[r00 * SY + mi + 8];
                float x03 = Xin[(r00 + 1) * SY + mi + 8];
                float x10 = Xin[r10 * SY + mi];
                float x11 = Xin[(r10 + 1) * SY + mi];
                float x12 = Xin[r10 * SY + mi + 8];
                float x13 = Xin[(r10 + 1) * SY + mi + 8];
                float h00 = bf16_trunc(x00), h01 = bf16_trunc(x01);
                float h02 = bf16_trunc(x02), h03 = bf16_trunc(x03);
                float h10 = bf16_trunc(x10), h11 = bf16_trunc(x11);
                float h12 = bf16_trunc(x12), h13 = bf16_trunc(x13);
                unsigned a0h = packbf2(h00, h01), a1h = packbf2(h02, h03);
                unsigned a2h = packbf2(h10, h11), a3h = packbf2(h12, h13);
                unsigned a0l = packbf2(x00 - h00, x01 - h01);
                unsigned a1l = packbf2(x02 - h02, x03 - h03);
                unsigned a2l = packbf2(x10 - h10, x11 - h11);
                unsigned a3l = packbf2(x12 - h12, x13 - h13);
                const uint2* w0p = Wc + (pp + tig) * SY;
                const uint2* w1p = Wc + (pp + tig + 4) * SY;
                #pragma unroll
                for (int nti = 0; nti < 8; nti++) {
                    int nb = (nh * 8 + nti) * 8 + gid;
                    uint2 b0 = w0p[nb], b1 = w1p[nb];
                    MMA_BF16(acc[nti], a0l, a1l, a2l, a3l, b0.x, b1.x);
                    MMA_BF16(acc[nti], a0h, a1h, a2h, a3h, b0.y, b1.y);
                    MMA_BF16(acc[nti], a0h, a1h, a2h, a3h, b0.x, b1.x);
                }
            }
        }
        __syncthreads();
        #pragma unroll
        for (int nti = 0; nti < 8; nti++) {
            int c0 = (nh * 8 + nti) * 8 + tig * 2;
            Yout[c0 * SY + mi] = leakyf(acc[nti][0]);
            Yout[(c0 + 1) * SY + mi] = leakyf(acc[nti][1]);
            Yout[c0 * SY + mi + 8] = leakyf(acc[nti][2]);
            Yout[(c0 + 1) * SY + mi + 8] = leakyf(acc[nti][3]);
        }
    }
    __syncthreads();

    {
        int col = tid >> 2, cq = tid & 3;
        float hj[8];
        #pragma unroll
        for (int j = 0; j < 8; j++) hj[j] = h2s[col * 8 + j];
        #pragma unroll 4
        for (int cc = 0; cc < 32; cc++) {
            int c = cq * 32 + cc;
            float s = sb2[c];
            #pragma unroll
            for (int j = 0; j < 8; j++) s += sw2[c * 8 + j] * hj[j];
            Xbuf[col * SY + c] = fmaxf(s, 0.f);
        }
    }
    __syncthreads();

    for (int e = tid; e < 1024; e += 512) {
        int pt = e >> 7, c = e & 127;
        const float* yr = Ybuf + c * SY + pt * 16;
        const float* sc = Xbuf + (pt * 16) * SY + c;
        float a = 0.f;
        #pragma unroll
        for (int k = 0; k < 16; k++) a += sc[k * SY] * yr[k];
        g_p2p[(size_t)(base + pt) * CO + c] = a;
    }
}

// ---------------- patch aggregation ----------------
__global__ void __launch_bounds__(128) k_patch(
    const float* __restrict__ n2w0, const float* __restrict__ n2b0,
    const float* __restrict__ n2w1, const float* __restrict__ n2b1,
    const float* __restrict__ n2w2, const float* __restrict__ n2b2,
    float* __restrict__ out)
{
    __shared__ float h2s[16][8];
    __shared__ int js[16];
    int q = blockIdx.x;
    int b = q / N1, n = q % N1;
    int tid = threadIdx.x;
    if (tid < 16) {
        int j = g_idx2[q * KN + tid];
        js[tid] = j;
        float dx0 = g_x1T[(b * N1 + j) * 3 + 0] - g_x1T[q * 3 + 0];
        float dx1 = g_x1T[(b * N1 + j) * 3 + 1] - g_x1T[q * 3 + 1];
        float dx2 = g_x1T[(b * N1 + j) * 3 + 2] - g_x1T[q * 3 + 2];
        float h[8];
        #pragma unroll
        for (int jj = 0; jj < 8; jj++) {
            float s = n2w0[jj * 3 + 0] * dx0 + n2w0[jj * 3 + 1] * dx1 + n2w0[jj * 3 + 2] * dx2 + n2b0[jj];
            h[jj] = fmaxf(s, 0.f);
        }
        #pragma unroll
        for (int jj = 0; jj < 8; jj++) {
            float s = n2b1[jj];
            #pragma unroll
            for (int m = 0; m < 8; m++) s += n2w1[jj * 8 + m] * h[m];
            h2s[tid][jj] = fmaxf(s, 0.f);
        }
    }
    __syncthreads();
    int c = tid;
    float w2r[8];
    #pragma unroll
    for (int j = 0; j < 8; j++) w2r[j] = n2w2[c * 8 + j];
    float bc = n2b2[c];
    float acc = 0.f;
    #pragma unroll
    for (int k = 0; k < KN; k++) {
        float s = bc;
        #pragma unroll
        for (int j = 0; j < 8; j++) s += w2r[j] * h2s[k][j];
        s = fmaxf(s, 0.f);
        acc += s * g_p2p[((size_t)b * N1 + js[k]) * CO + c];
    }
    out[(size_t)b * CO * N1 + (size_t)c * N1 + n] = acc;
}

// ---------------- launch ----------------
extern "C" void kernel_launch(void* const* d_in, const int* in_sizes, int n_in,
                              void* d_out, int out_size)
{
    int s = (n_in >= 31) ? 0 : -2;
    const float* xyz1 = (const float*)d_in[0];
    const float* xyz2 = (const float*)d_in[1];
    const float* pts1 = (const float*)d_in[2];
    const float* pts2 = (const float*)d_in[3];
    const float* vel1 = (const float*)d_in[4];
    const float* fcc  = (const float*)d_in[8 + s];
    const float* fcv  = (const float*)d_in[9 + s];
    const float* wxyz = (const float*)d_in[10 + s];
    const float* wpts = (const float*)d_in[12 + s];
    const float* mw0 = (const float*)d_in[13 + s];
    const float* mb0 = (const float*)d_in[14 + s];
    const float* mw1 = (const float*)d_in[15 + s];
    const float* mb1 = (const float*)d_in[16 + s];
    const float* mw2 = (const float*)d_in[17 + s];
    const float* mb2 = (const float*)d_in[18 + s];
    const float* n1w0 = (const float*)d_in[19 + s];
    const float* n1b0 = (const float*)d_in[20 + s];
    const float* n2w0 = (const float*)d_in[21 + s];
    const float* n2b0 = (const float*)d_in[22 + s];
    const float* n1w1 = (const float*)d_in[23 + s];
    const float* n1b1 = (const float*)d_in[24 + s];
    const float* n2w1 = (const float*)d_in[25 + s];
    const float* n2b1 = (const float*)d_in[26 + s];
    const float* n1w2 = (const float*)d_in[27 + s];
    const float* n1b2 = (const float*)d_in[28 + s];
    const float* n2w2 = (const float*)d_in[29 + s];
    const float* n2b2 = (const float*)d_in[30 + s];

    float* out = (float*)d_out;
    const int patch_elems = BATCH * CO * N1;
    const int vw_elems = BATCH * N1 * 3;
    float* out_vw = (out_size >= patch_elems + vw_elems) ? (out + patch_elems) : nullptr;

    cudaFuncSetAttribute(k_mlp_tc, cudaFuncAttributeMaxDynamicSharedMemorySize, (int)MLP2_SMEM);
    cudaFuncSetAttribute(k_dist_tc, cudaFuncAttributeMaxDynamicSharedMemorySize, (int)DIST_SMEM);

    const int prep_total = 2 * BATCH * CP * N1 + 2 * BATCH * 3 * N1;
    dim3 gg(N2 / 128, N1 / 128, BATCH);
    dim3 gt(N1 / 32, 2 * BATCH * 2);

    // order: topk0 is the 4th launch -> ncu lands on the new top-k
    k_prep<<<(prep_total + 255) / 256, 256>>>(xyz1, xyz2, pts1, pts2, wxyz, wpts);
    k_normsAB<<<(BATCH * 4096 + 127) / 128, 128>>>();
    k_dist_tc<<<gg, 256, DIST_SMEM>>>(0);
    k_topk<<<BATCH * N1, 256>>>(0);
    k_rigid<<<(BATCH * N1 + 127) / 128, 128>>>(xyz1, vel1, fcc, fcv, out_vw);
    k_nc<<<(BATCH * N1 + 127) / 128, 128>>>();
    k_transp<<<gt, 256>>>(pts1, pts2);
    k_wprep<<<108, 256>>>(mw0, mw1, mw2);
    k_mlp_tc<<<(BATCH * N1) / TNP, 512, MLP2_SMEM>>>(mb0, mb1, mb2,
                                                     n1w0, n1b0, n1w1, n1b1, n1w2, n1b2);
    k_comb<<<(BATCH * CP * N1 + 255) / 256, 256>>>();
    k_dist_tc<<<gg, 256, DIST_SMEM>>>(1);
    k_topk<<<BATCH * N1, 256>>>(1);
    k_patch<<<BATCH * N1, 128>>>(n2w0, n2b0, n2w1, n2b1, n2w2, n2b2, out);
}